// round 10
// baseline (speedup 1.0000x reference)
#include <cuda_runtime.h>
#include <cstdint>

#define Tn 256
#define Bn 64
#define Dn 768
#define Rn 2048
#define KS 8
#define KC (Rn / KS)   // 256 k per split

// Scratch (static __device__ arrays: allocation-guard safe)
__device__ float g_P[(size_t)Tn * Rn * Bn];   // [t][r][b] : input projection + bias
__device__ float g_x0[Rn * Bn];               // state ping [r][b]
__device__ float g_x1[Rn * Bn];               // state pong [r][b]

// ---- packed f32x2 helpers (Blackwell sm_103a) ----
__device__ __forceinline__ void ffma2(unsigned long long& d, unsigned long long a, unsigned long long b) {
    asm("fma.rn.f32x2 %0, %1, %2, %0;" : "+l"(d) : "l"(a), "l"(b));
}
__device__ __forceinline__ unsigned long long pack2(float lo, float hi) {
    unsigned long long r;
    asm("mov.b64 %0, {%1, %2};" : "=l"(r) : "f"(lo), "f"(hi));
    return r;
}
__device__ __forceinline__ void unpack2(unsigned long long v, float& lo, float& hi) {
    asm("mov.b64 {%0, %1}, %2;" : "=f"(lo), "=f"(hi) : "l"(v));
}

// ---- cluster / DSMEM helpers ----
__device__ __forceinline__ uint32_t smem_u32(const void* p) {
    uint32_t a;
    asm("{ .reg .u64 t; cvta.to.shared.u64 t, %1; cvt.u32.u64 %0, t; }" : "=r"(a) : "l"(p));
    return a;
}
__device__ __forceinline__ uint32_t mapa_cluster(uint32_t local_addr, uint32_t rank) {
    uint32_t r;
    asm("mapa.shared::cluster.u32 %0, %1, %2;" : "=r"(r) : "r"(local_addr), "r"(rank));
    return r;
}
__device__ __forceinline__ float ld_dsmem_f32(uint32_t addr) {
    float v;
    asm volatile("ld.shared::cluster.f32 %0, [%1];" : "=f"(v) : "r"(addr));
    return v;
}
#define CLUSTER_ARRIVE() asm volatile("barrier.cluster.arrive.aligned;" ::: "memory")
#define CLUSTER_WAIT()   asm volatile("barrier.cluster.wait.aligned;" ::: "memory")

// accurate tanh independent of fast-math flags (~1e-6 rel)
__device__ __forceinline__ float tanh_acc(float x) {
    float ax = fabsf(x);
    float e  = __expf(-2.0f * ax);
    float r  = (1.0f - e) / (1.0f + e);
    return copysignf(r, x);
}

// ---------------------------------------------------------------------------
// init: xT[r][b] = initial_state[r]
// ---------------------------------------------------------------------------
__global__ void init_x_kernel(const float* __restrict__ init_state) {
    int i = blockIdx.x * blockDim.x + threadIdx.x;
    if (i < Rn * Bn) g_x0[i] = init_state[i >> 6];
}

// ---------------------------------------------------------------------------
// proj: g_P[t][r][b] = sum_d inp[t][b][d] * Win[r][d] + bias[r]
// grid (Rn/64, Tn), block 128.  (unchanged)
// ---------------------------------------------------------------------------
__global__ __launch_bounds__(128) void proj_kernel(const float* __restrict__ inp,
                                                   const float* __restrict__ win,
                                                   const float* __restrict__ bias) {
    __shared__ __align__(16) float As[16][64];   // [k][b]
    __shared__ __align__(16) float Bs[16][64];   // [k][r]
    const int t  = blockIdx.y;
    const int rt = blockIdx.x;
    const int tid = threadIdx.x;
    const int tx = tid & 15;        // b-group
    const int ty = tid >> 4;        // r-group

    unsigned long long acc[4][4];
#pragma unroll
    for (int i = 0; i < 4; i++)
#pragma unroll
        for (int j = 0; j < 4; j++) acc[i][j] = 0ULL;

    const int lrow = tid >> 1;
    const int lcol = (tid & 1) * 8;
    const float* Ap = inp + (size_t)t * Bn * Dn + (size_t)lrow * Dn + lcol;
    const float* Bp = win + (size_t)rt * 64 * Dn + (size_t)lrow * Dn + lcol;

    for (int kk = 0; kk < Dn; kk += 16) {
        float4 a0 = *(const float4*)(Ap + kk);
        float4 a1 = *(const float4*)(Ap + kk + 4);
        float4 b0 = *(const float4*)(Bp + kk);
        float4 b1 = *(const float4*)(Bp + kk + 4);
        __syncthreads();
        As[lcol + 0][lrow] = a0.x; As[lcol + 1][lrow] = a0.y;
        As[lcol + 2][lrow] = a0.z; As[lcol + 3][lrow] = a0.w;
        As[lcol + 4][lrow] = a1.x; As[lcol + 5][lrow] = a1.y;
        As[lcol + 6][lrow] = a1.z; As[lcol + 7][lrow] = a1.w;
        Bs[lcol + 0][lrow] = b0.x; Bs[lcol + 1][lrow] = b0.y;
        Bs[lcol + 2][lrow] = b0.z; Bs[lcol + 3][lrow] = b0.w;
        Bs[lcol + 4][lrow] = b1.x; Bs[lcol + 5][lrow] = b1.y;
        Bs[lcol + 6][lrow] = b1.z; Bs[lcol + 7][lrow] = b1.w;
        __syncthreads();
#pragma unroll
        for (int k = 0; k < 16; k++) {
            float4 av = *(const float4*)&As[k][tx * 4];
            unsigned long long ad0 = pack2(av.x, av.x);
            unsigned long long ad1 = pack2(av.y, av.y);
            unsigned long long ad2 = pack2(av.z, av.z);
            unsigned long long ad3 = pack2(av.w, av.w);
            ulonglong2 w0 = *(const ulonglong2*)&Bs[k][ty * 8];
            ulonglong2 w1 = *(const ulonglong2*)&Bs[k][ty * 8 + 4];
            ffma2(acc[0][0], ad0, w0.x); ffma2(acc[0][1], ad0, w0.y);
            ffma2(acc[0][2], ad0, w1.x); ffma2(acc[0][3], ad0, w1.y);
            ffma2(acc[1][0], ad1, w0.x); ffma2(acc[1][1], ad1, w0.y);
            ffma2(acc[1][2], ad1, w1.x); ffma2(acc[1][3], ad1, w1.y);
            ffma2(acc[2][0], ad2, w0.x); ffma2(acc[2][1], ad2, w0.y);
            ffma2(acc[2][2], ad2, w1.x); ffma2(acc[2][3], ad2, w1.y);
            ffma2(acc[3][0], ad3, w0.x); ffma2(acc[3][1], ad3, w0.y);
            ffma2(acc[3][2], ad3, w1.x); ffma2(acc[3][3], ad3, w1.y);
        }
    }

    float c[4][8];
#pragma unroll
    for (int bb = 0; bb < 4; bb++)
#pragma unroll
        for (int rp = 0; rp < 4; rp++) {
            float lo, hi;
            unpack2(acc[bb][rp], lo, hi);
            c[bb][rp * 2] = lo;
            c[bb][rp * 2 + 1] = hi;
        }
#pragma unroll
    for (int j = 0; j < 8; j++) {
        int r = rt * 64 + ty * 8 + j;
        float bv = bias[r];
        float4 o = make_float4(c[0][j] + bv, c[1][j] + bv, c[2][j] + bv, c[3][j] + bv);
        *(float4*)&g_P[((size_t)t * Rn + r) * Bn + tx * 4] = o;
    }
}

// ---------------------------------------------------------------------------
// fused recurrence step via 8-CTA cluster (one cluster per 32-row r-tile).
// grid (KS=8, 64), cluster (8,1,1), block 256  (2x warps vs R8 at same CTA
// count -> same L2 traffic, double latency hiding).
// Per-thread micro-tile 2b x 4r: inner loop per k =
//   LDS.64(x pair) + LDS.128(w, warp-uniform broadcast) + 2 pack + 4 ffma2.
// Cluster protocol identical to R8 (two arrive/wait pairs, DSMEM reduce).
// ---------------------------------------------------------------------------
__global__ __launch_bounds__(256) __cluster_dims__(KS, 1, 1)
void step_cluster_kernel(const float* __restrict__ wres,
                         const int* __restrict__ lengths,
                         float* __restrict__ out,
                         int t) {
    __shared__ __align__(16) float Xs[32 * 64];   // [k][b]; reused as partial [32r][64b]
    __shared__ __align__(16) float Ws[32 * 32];   // [k][r]
    const int ks  = blockIdx.x;    // cluster rank = k-slice
    const int rt  = blockIdx.y;    // 0..63
    const int tid = threadIdx.x;   // 0..255
    const int bg  = tid & 31;      // b = bg*2 + bb
    const int rg  = tid >> 5;      // r = rt*32 + rg*4 + j   (rg 0..7)

    const float* xsrc = (t & 1) ? g_x1 : g_x0;
    float*       xdst = (t & 1) ? g_x0 : g_x1;
    const int r0 = rt * 32;
    const int k0 = ks * KC;

    unsigned long long acc[2][2];   // [bb][r-pair]
    acc[0][0] = acc[0][1] = acc[1][0] = acc[1][1] = 0ULL;

    // W loader: lr = tid&31 (row in tile), lk = (tid>>5)*4 (k offset) -> conflict-free stores
    const int lr = tid & 31;
    const int lk = (tid >> 5) * 4;
    const float* wp = wres + (size_t)(r0 + lr) * Rn + k0 + lk;

    // prefetch chunk 0 (X: 2 float4/thread, W: 1 float4/thread)
    float4 xa, xb, wv;
    {
        const float4* xg = (const float4*)(xsrc + (size_t)k0 * Bn);
        xa = xg[tid]; xb = xg[tid + 256];
        wv = *(const float4*)(wp);
    }

    for (int kc = 0; kc < KC; kc += 32) {
        __syncthreads();
        ((float4*)Xs)[tid]       = xa;
        ((float4*)Xs)[tid + 256] = xb;
        Ws[(lk + 0) * 32 + lr] = wv.x;
        Ws[(lk + 1) * 32 + lr] = wv.y;
        Ws[(lk + 2) * 32 + lr] = wv.z;
        Ws[(lk + 3) * 32 + lr] = wv.w;
        __syncthreads();
        if (kc + 32 < KC) {   // prefetch next chunk while computing
            const float4* xg = (const float4*)(xsrc + (size_t)(k0 + kc + 32) * Bn);
            xa = xg[tid]; xb = xg[tid + 256];
            wv = *(const float4*)(wp + kc + 32);
        }
#pragma unroll
        for (int k = 0; k < 32; k++) {
            float2 xq = *(const float2*)&Xs[k * 64 + bg * 2];
            unsigned long long a0 = pack2(xq.x, xq.x);
            unsigned long long a1 = pack2(xq.y, xq.y);
            ulonglong2 w = *(const ulonglong2*)&Ws[k * 32 + rg * 4];   // warp-uniform -> broadcast
            ffma2(acc[0][0], a0, w.x); ffma2(acc[0][1], a0, w.y);
            ffma2(acc[1][0], a1, w.x); ffma2(acc[1][1], a1, w.y);
        }
    }

    // s[bb][j] = partial for (b = bg*2+bb, r = r0+rg*4+j)
    float s[2][4];
#pragma unroll
    for (int bb = 0; bb < 2; bb++) {
        unpack2(acc[bb][0], s[bb][0], s[bb][1]);
        unpack2(acc[bb][1], s[bb][2], s[bb][3]);
    }

    // store partial tile [32r][64b] into own SMEM (reusing Xs)
    __syncthreads();   // all Xs reads done before overwrite
#pragma unroll
    for (int j = 0; j < 4; j++) {
        float2 o = make_float2(s[0][j], s[1][j]);
        *(float2*)&Xs[(rg * 4 + j) * 64 + bg * 2] = o;
    }
    __syncthreads();   // partial complete before cluster arrive (release)
    CLUSTER_ARRIVE();  // barrier #1 arrive: my partial is published

    // hide global loads for the tail behind cluster arrival skew.
    // This CTA reduces rows [r0 + ks*4, r0 + ks*4 + 4): 256 values, 1/thread.
    const int bT   = tid >> 2;            // 0..63
    const int rloc = ks * 4 + (tid & 3);  // row within 32-row tile
    const int rT   = r0 + rloc;
    const float pv   = g_P[((size_t)t * Rn + rT) * Bn + bT];
    const float xo   = xsrc[(size_t)rT * Bn + bT];
    const int   lenv = lengths[bT];

    CLUSTER_WAIT();    // barrier #1 wait: all partials visible

    // pull all peer partials into registers (8 DSMEM loads, MLP-overlapped)
    const uint32_t base = smem_u32(Xs);
    const uint32_t off  = base + (uint32_t)(rloc * 64 + bT) * 4u;
    float pr[KS];
#pragma unroll
    for (int peer = 0; peer < KS; peer++)
        pr[peer] = ld_dsmem_f32(mapa_cluster(off, (uint32_t)peer));

    CLUSTER_ARRIVE();  // barrier #2 arrive: done reading peer SMEM

    // epilogue math + global stores overlap the second barrier window
    float sum = pv;
#pragma unroll
    for (int peer = 0; peer < KS; peer++) sum += pr[peer];   // fixed order: deterministic
    const float m  = (lenv > t) ? 0.5f : 0.0f;               // mask * lr (lr = 1-lr = 0.5)
    const float xn = m * (xo + tanh_acc(sum));
    xdst[(size_t)rT * Bn + bT] = xn;
    out[((size_t)bT * Tn + t) * Rn + rT] = xn;

    CLUSTER_WAIT();    // barrier #2 wait: safe to exit (no peer still reads my SMEM)
}

// ---------------------------------------------------------------------------
// launch: init + proj + 256 clustered step kernels — all graph-capturable
// ---------------------------------------------------------------------------
extern "C" void kernel_launch(void* const* d_in, const int* in_sizes, int n_in,
                              void* d_out, int out_size) {
    const float* inp     = (const float*)d_in[0];  // [T,B,D]
    const int*   lengths = (const int*)d_in[1];    // [B]
    const float* win     = (const float*)d_in[2];  // [R,D]
    const float* wres    = (const float*)d_in[3];  // [R,R]
    const float* bias    = (const float*)d_in[4];  // [R]
    const float* x0in    = (const float*)d_in[5];  // [R]
    float* out = (float*)d_out;                    // [B,T,R]

    init_x_kernel<<<(Rn * Bn + 255) / 256, 256>>>(x0in);
    proj_kernel<<<dim3(Rn / 64, Tn), 128>>>(inp, win, bias);
    for (int t = 0; t < Tn; t++) {
        step_cluster_kernel<<<dim3(KS, 64), 256>>>(wres, lengths, out, t);
    }
}

// round 12
// speedup vs baseline: 2.4642x; 2.4642x over previous
#include <cuda_runtime.h>
#include <cuda_bf16.h>
#include <cstdint>

#define Tn 256
#define Bn 64
#define Dn 768
#define Rn 2048

#define KSPLIT 4
#define KCTA   (Rn / KSPLIT)   // 512
#define MCTA   64              // rows per CTA
#define NRT    (Rn / MCTA)     // 32 r-tiles
#define KCH    32              // k per chunk
#define NCHUNK (KCTA / KCH)    // 16
#define STRIDE 40              // bf16 elems per smem row (32 + 8 pad) -> conflict-free frags
#define PLANE  (64 * STRIDE * 2)   // 5120 B per plane
#define BUFSZ  (4 * PLANE)         // 20480 B per buffer (Whi,Wlo,Xhi,Xlo)

// Scratch (static __device__ arrays: allocation-guard safe)
__device__ float g_P[(size_t)Tn * Rn * Bn];            // [t][r][b] proj + bias
__device__ uint4 g_Whi4[(size_t)Rn * Rn / 8];          // bf16 W_hi [r][k]
__device__ uint4 g_Wlo4[(size_t)Rn * Rn / 8];          // bf16 W_lo [r][k]
__device__ uint4 g_xh4[2][(size_t)Bn * Rn / 8];        // bf16 x_hi [b][r] ping-pong
__device__ uint4 g_xl4[2][(size_t)Bn * Rn / 8];        // bf16 x_lo [b][r] ping-pong

// ---- packed f32x2 helpers (proj kernel) ----
__device__ __forceinline__ void ffma2(unsigned long long& d, unsigned long long a, unsigned long long b) {
    asm("fma.rn.f32x2 %0, %1, %2, %0;" : "+l"(d) : "l"(a), "l"(b));
}
__device__ __forceinline__ unsigned long long pack2(float lo, float hi) {
    unsigned long long r;
    asm("mov.b64 %0, {%1, %2};" : "=l"(r) : "f"(lo), "f"(hi));
    return r;
}
__device__ __forceinline__ void unpack2(unsigned long long v, float& lo, float& hi) {
    asm("mov.b64 {%0, %1}, %2;" : "=f"(lo), "=f"(hi) : "l"(v));
}

// ---- cluster / DSMEM helpers (R8-proven) ----
__device__ __forceinline__ uint32_t smem_u32(const void* p) {
    uint32_t a;
    asm("{ .reg .u64 t; cvta.to.shared.u64 t, %1; cvt.u32.u64 %0, t; }" : "=r"(a) : "l"(p));
    return a;
}
__device__ __forceinline__ uint32_t mapa_cluster(uint32_t local_addr, uint32_t rank) {
    uint32_t r;
    asm("mapa.shared::cluster.u32 %0, %1, %2;" : "=r"(r) : "r"(local_addr), "r"(rank));
    return r;
}
__device__ __forceinline__ float ld_dsmem_f32(uint32_t addr) {
    float v;
    asm volatile("ld.shared::cluster.f32 %0, [%1];" : "=f"(v) : "r"(addr));
    return v;
}
#define CLUSTER_ARRIVE() asm volatile("barrier.cluster.arrive.aligned;" ::: "memory")
#define CLUSTER_WAIT()   asm volatile("barrier.cluster.wait.aligned;" ::: "memory")

// accurate tanh independent of fast-math flags (~1e-6 rel)
__device__ __forceinline__ float tanh_acc(float x) {
    float ax = fabsf(x);
    float e  = __expf(-2.0f * ax);
    float r  = (1.0f - e) / (1.0f + e);
    return copysignf(r, x);
}

// m16n8k16 row.col bf16 MMA, fp32 accumulate in-place
__device__ __forceinline__ void mma16816(float* d, uint32_t a0, uint32_t a1, uint32_t a2, uint32_t a3,
                                         uint32_t b0, uint32_t b1) {
    asm volatile(
        "mma.sync.aligned.m16n8k16.row.col.f32.bf16.bf16.f32 "
        "{%0,%1,%2,%3}, {%4,%5,%6,%7}, {%8,%9}, {%0,%1,%2,%3};"
        : "+f"(d[0]), "+f"(d[1]), "+f"(d[2]), "+f"(d[3])
        : "r"(a0), "r"(a1), "r"(a2), "r"(a3), "r"(b0), "r"(b1));
}

// ---------------------------------------------------------------------------
// prep: split W into bf16 hi/lo (deterministic, runs every replay)
// ---------------------------------------------------------------------------
__global__ void prep_w_kernel(const float* __restrict__ w) {
    size_t i = (size_t)blockIdx.x * blockDim.x + threadIdx.x;   // one uint4 (8 bf16)
    if (i >= (size_t)Rn * Rn / 8) return;
    const float4* w4 = (const float4*)w;
    float4 f0 = w4[i * 2], f1 = w4[i * 2 + 1];
    float f[8] = {f0.x, f0.y, f0.z, f0.w, f1.x, f1.y, f1.z, f1.w};
    union { __nv_bfloat16 h[8]; uint4 v; } hi, lo;
#pragma unroll
    for (int j = 0; j < 8; j++) {
        hi.h[j] = __float2bfloat16(f[j]);
        lo.h[j] = __float2bfloat16(f[j] - __bfloat162float(hi.h[j]));
    }
    g_Whi4[i] = hi.v;
    g_Wlo4[i] = lo.v;
}

// ---------------------------------------------------------------------------
// init: x_hi/x_lo parity-0 buffers from initial_state
// ---------------------------------------------------------------------------
__global__ void init_x_kernel(const float* __restrict__ init_state) {
    int i = blockIdx.x * blockDim.x + threadIdx.x;   // b*Rn + r
    if (i < Bn * Rn) {
        float v = init_state[i & (Rn - 1)];
        __nv_bfloat16 h = __float2bfloat16(v);
        ((__nv_bfloat16*)g_xh4[0])[i] = h;
        ((__nv_bfloat16*)g_xl4[0])[i] = __float2bfloat16(v - __bfloat162float(h));
    }
}

// ---------------------------------------------------------------------------
// proj (unchanged, fp32): g_P[t][r][b] = inp[t,b,:]·Win[r,:] + bias[r]
// ---------------------------------------------------------------------------
__global__ __launch_bounds__(128) void proj_kernel(const float* __restrict__ inp,
                                                   const float* __restrict__ win,
                                                   const float* __restrict__ bias) {
    __shared__ __align__(16) float As[16][64];
    __shared__ __align__(16) float Bs[16][64];
    const int t  = blockIdx.y;
    const int rt = blockIdx.x;
    const int tid = threadIdx.x;
    const int tx = tid & 15;
    const int ty = tid >> 4;

    unsigned long long acc[4][4];
#pragma unroll
    for (int i = 0; i < 4; i++)
#pragma unroll
        for (int j = 0; j < 4; j++) acc[i][j] = 0ULL;

    const int lrow = tid >> 1;
    const int lcol = (tid & 1) * 8;
    const float* Ap = inp + (size_t)t * Bn * Dn + (size_t)lrow * Dn + lcol;
    const float* Bp = win + (size_t)rt * 64 * Dn + (size_t)lrow * Dn + lcol;

    for (int kk = 0; kk < Dn; kk += 16) {
        float4 a0 = *(const float4*)(Ap + kk);
        float4 a1 = *(const float4*)(Ap + kk + 4);
        float4 b0 = *(const float4*)(Bp + kk);
        float4 b1 = *(const float4*)(Bp + kk + 4);
        __syncthreads();
        As[lcol + 0][lrow] = a0.x; As[lcol + 1][lrow] = a0.y;
        As[lcol + 2][lrow] = a0.z; As[lcol + 3][lrow] = a0.w;
        As[lcol + 4][lrow] = a1.x; As[lcol + 5][lrow] = a1.y;
        As[lcol + 6][lrow] = a1.z; As[lcol + 7][lrow] = a1.w;
        Bs[lcol + 0][lrow] = b0.x; Bs[lcol + 1][lrow] = b0.y;
        Bs[lcol + 2][lrow] = b0.z; Bs[lcol + 3][lrow] = b0.w;
        Bs[lcol + 4][lrow] = b1.x; Bs[lcol + 5][lrow] = b1.y;
        Bs[lcol + 6][lrow] = b1.z; Bs[lcol + 7][lrow] = b1.w;
        __syncthreads();
#pragma unroll
        for (int k = 0; k < 16; k++) {
            float4 av = *(const float4*)&As[k][tx * 4];
            unsigned long long ad0 = pack2(av.x, av.x);
            unsigned long long ad1 = pack2(av.y, av.y);
            unsigned long long ad2 = pack2(av.z, av.z);
            unsigned long long ad3 = pack2(av.w, av.w);
            ulonglong2 w0 = *(const ulonglong2*)&Bs[k][ty * 8];
            ulonglong2 w1 = *(const ulonglong2*)&Bs[k][ty * 8 + 4];
            ffma2(acc[0][0], ad0, w0.x); ffma2(acc[0][1], ad0, w0.y);
            ffma2(acc[0][2], ad0, w1.x); ffma2(acc[0][3], ad0, w1.y);
            ffma2(acc[1][0], ad1, w0.x); ffma2(acc[1][1], ad1, w0.y);
            ffma2(acc[1][2], ad1, w1.x); ffma2(acc[1][3], ad1, w1.y);
            ffma2(acc[2][0], ad2, w0.x); ffma2(acc[2][1], ad2, w0.y);
            ffma2(acc[2][2], ad2, w1.x); ffma2(acc[2][3], ad2, w1.y);
            ffma2(acc[3][0], ad3, w0.x); ffma2(acc[3][1], ad3, w0.y);
            ffma2(acc[3][2], ad3, w1.x); ffma2(acc[3][3], ad3, w1.y);
        }
    }

    float c[4][8];
#pragma unroll
    for (int bb = 0; bb < 4; bb++)
#pragma unroll
        for (int rp = 0; rp < 4; rp++) {
            float lo, hi;
            unpack2(acc[bb][rp], lo, hi);
            c[bb][rp * 2] = lo;
            c[bb][rp * 2 + 1] = hi;
        }
#pragma unroll
    for (int j = 0; j < 8; j++) {
        int r = rt * 64 + ty * 8 + j;
        float bv = bias[r];
        float4 o = make_float4(c[0][j] + bv, c[1][j] + bv, c[2][j] + bv, c[3][j] + bv);
        *(float4*)&g_P[((size_t)t * Rn + r) * Bn + tx * 4] = o;
    }
}

// ---------------------------------------------------------------------------
// step: HMMA split-bf16 recurrence GEMM, cluster(4) k-split, DSMEM reduce.
// grid (KSPLIT=4, NRT=32) = 128 CTAs, block 256 (8 warps = 4 m-tiles x 2 n-halves).
// D = Whi*xhi + Whi*xlo + Wlo*xhi, fp32 accum in registers, K=512 per CTA.
// ---------------------------------------------------------------------------
__global__ __launch_bounds__(256) __cluster_dims__(KSPLIT, 1, 1)
void step_hmma_kernel(const int* __restrict__ lengths,
                      float* __restrict__ out,
                      int t) {
    __shared__ __align__(16) char sAll[2 * BUFSZ];   // 40960 B
    const int ks  = blockIdx.x;   // cluster rank = k-slice
    const int rt  = blockIdx.y;
    const int tid = threadIdx.x;
    const int wid = tid >> 5, lane = tid & 31;
    const int g = lane >> 2, tig = lane & 3;
    const int mt = wid & 3, nh = wid >> 2;
    const int r0 = rt * MCTA, k0 = ks * KCTA;

    const __nv_bfloat16* Wh  = (const __nv_bfloat16*)g_Whi4;
    const __nv_bfloat16* Wl  = (const __nv_bfloat16*)g_Wlo4;
    const __nv_bfloat16* xhs = (const __nv_bfloat16*)g_xh4[t & 1];
    const __nv_bfloat16* xls = (const __nv_bfloat16*)g_xl4[t & 1];
    __nv_bfloat16* xhd = (__nv_bfloat16*)g_xh4[(t & 1) ^ 1];
    __nv_bfloat16* xld = (__nv_bfloat16*)g_xl4[(t & 1) ^ 1];

    float d[4][4];
#pragma unroll
    for (int i = 0; i < 4; i++)
#pragma unroll
        for (int j = 0; j < 4; j++) d[i][j] = 0.0f;

    // staging: one uint4 per thread per plane per chunk (64 rows x 4 uint4)
    const int srow = tid >> 2;
    const int sc4  = tid & 3;
    const int soff = srow * (STRIDE * 2) + sc4 * 16;   // bytes within plane

    uint4 vwh, vwl, vxh, vxl;
    {
        const int kk = k0 + sc4 * 8;
        vwh = *(const uint4*)(Wh + (size_t)(r0 + srow) * Rn + kk);
        vwl = *(const uint4*)(Wl + (size_t)(r0 + srow) * Rn + kk);
        vxh = *(const uint4*)(xhs + (size_t)srow * Rn + kk);
        vxl = *(const uint4*)(xls + (size_t)srow * Rn + kk);
    }

    const int ar0 = (mt * 16 + g) * (STRIDE * 2);
    const int ar1 = (mt * 16 + g + 8) * (STRIDE * 2);

    for (int c = 0; c < NCHUNK; c++) {
        char* buf = sAll + (c & 1) * BUFSZ;
        __syncthreads();
        *(uint4*)(buf + 0 * PLANE + soff) = vwh;
        *(uint4*)(buf + 1 * PLANE + soff) = vwl;
        *(uint4*)(buf + 2 * PLANE + soff) = vxh;
        *(uint4*)(buf + 3 * PLANE + soff) = vxl;
        __syncthreads();
        if (c + 1 < NCHUNK) {
            const int kk = k0 + (c + 1) * KCH + sc4 * 8;
            vwh = *(const uint4*)(Wh + (size_t)(r0 + srow) * Rn + kk);
            vwl = *(const uint4*)(Wl + (size_t)(r0 + srow) * Rn + kk);
            vxh = *(const uint4*)(xhs + (size_t)srow * Rn + kk);
            vxl = *(const uint4*)(xls + (size_t)srow * Rn + kk);
        }
        const char* AH = buf;
        const char* AL = buf + PLANE;
        const char* BH = buf + 2 * PLANE;
        const char* BL = buf + 3 * PLANE;
#pragma unroll
        for (int ki = 0; ki < KCH / 16; ki++) {
            const int acol = (ki * 16 + 2 * tig) * 2;   // bytes
            uint32_t ah0 = *(const uint32_t*)(AH + ar0 + acol);
            uint32_t ah1 = *(const uint32_t*)(AH + ar1 + acol);
            uint32_t ah2 = *(const uint32_t*)(AH + ar0 + acol + 16);
            uint32_t ah3 = *(const uint32_t*)(AH + ar1 + acol + 16);
            uint32_t al0 = *(const uint32_t*)(AL + ar0 + acol);
            uint32_t al1 = *(const uint32_t*)(AL + ar1 + acol);
            uint32_t al2 = *(const uint32_t*)(AL + ar0 + acol + 16);
            uint32_t al3 = *(const uint32_t*)(AL + ar1 + acol + 16);
#pragma unroll
            for (int nt = 0; nt < 4; nt++) {
                const int brow = (nh * 32 + nt * 8 + g) * (STRIDE * 2);
                uint32_t bh0 = *(const uint32_t*)(BH + brow + acol);
                uint32_t bh1 = *(const uint32_t*)(BH + brow + acol + 16);
                uint32_t bl0 = *(const uint32_t*)(BL + brow + acol);
                uint32_t bl1 = *(const uint32_t*)(BL + brow + acol + 16);
                mma16816(d[nt], ah0, ah1, ah2, ah3, bh0, bh1);   // Whi*xhi
                mma16816(d[nt], ah0, ah1, ah2, ah3, bl0, bl1);   // Whi*xlo
                mma16816(d[nt], al0, al1, al2, al3, bh0, bh1);   // Wlo*xhi
            }
        }
    }

    // partial [64r][64n] fp32 at sAll[0..16384) (buf0 region; last chunk used buf1)
    float* part = (float*)sAll;
#pragma unroll
    for (int nt = 0; nt < 4; nt++) {
        const int n = nh * 32 + nt * 8 + 2 * tig;
        const int r = mt * 16 + g;
        *(float2*)&part[r * 64 + n]       = make_float2(d[nt][0], d[nt][1]);
        *(float2*)&part[(r + 8) * 64 + n] = make_float2(d[nt][2], d[nt][3]);
    }
    __syncthreads();   // partial complete (release)
    CLUSTER_ARRIVE();  // barrier #1: my partial is published

    // prefetch epilogue operands behind arrival skew.
    // This CTA reduces rows [r0 + ks*16, +16): 1024 values, 4 consecutive r per thread.
    const int b    = tid & 63;
    const int rloc = ks * 16 + (tid >> 6) * 4;
    const int r    = r0 + rloc;
    float pv[4], xo[4];
#pragma unroll
    for (int j = 0; j < 4; j++) {
        pv[j] = g_P[((size_t)t * Rn + r + j) * Bn + b];
        xo[j] = __bfloat162float(xhs[(size_t)b * Rn + r + j])
              + __bfloat162float(xls[(size_t)b * Rn + r + j]);
    }
    const int len = lengths[b];

    CLUSTER_WAIT();    // barrier #1 wait: all partials visible

    const uint32_t pbase = smem_u32(sAll);
    float pr[KSPLIT][4];
#pragma unroll
    for (int peer = 0; peer < KSPLIT; peer++) {
#pragma unroll
        for (int j = 0; j < 4; j++) {
            uint32_t addr = mapa_cluster(pbase + (uint32_t)((rloc + j) * 64 + b) * 4u, (uint32_t)peer);
            pr[peer][j] = ld_dsmem_f32(addr);
        }
    }

    CLUSTER_ARRIVE();  // barrier #2: done reading peer SMEM

    const float m = (len > t) ? 0.5f : 0.0f;   // mask * lr (lr = 1-lr = 0.5)
    float4 ov;
#pragma unroll
    for (int j = 0; j < 4; j++) {
        float sum = pv[j];
#pragma unroll
        for (int peer = 0; peer < KSPLIT; peer++) sum += pr[peer][j];   // fixed order
        const float xn = m * (xo[j] + tanh_acc(sum));
        ((float*)&ov)[j] = xn;
        const __nv_bfloat16 h = __float2bfloat16(xn);
        xhd[(size_t)b * Rn + r + j] = h;
        xld[(size_t)b * Rn + r + j] = __float2bfloat16(xn - __bfloat162float(h));
    }
    *(float4*)&out[((size_t)b * Tn + t) * Rn + r] = ov;

    CLUSTER_WAIT();    // barrier #2 wait: safe to exit
}

// ---------------------------------------------------------------------------
// launch: prep + init + proj + 256 HMMA step kernels — all graph-capturable
// ---------------------------------------------------------------------------
extern "C" void kernel_launch(void* const* d_in, const int* in_sizes, int n_in,
                              void* d_out, int out_size) {
    const float* inp     = (const float*)d_in[0];  // [T,B,D]
    const int*   lengths = (const int*)d_in[1];    // [B]
    const float* win     = (const float*)d_in[2];  // [R,D]
    const float* wres    = (const float*)d_in[3];  // [R,R]
    const float* bias    = (const float*)d_in[4];  // [R]
    const float* x0in    = (const float*)d_in[5];  // [R]
    float* out = (float*)d_out;                    // [B,T,R]

    prep_w_kernel<<<(Rn * Rn / 8 + 255) / 256, 256>>>(wres);
    init_x_kernel<<<(Bn * Rn + 255) / 256, 256>>>(x0in);
    proj_kernel<<<dim3(Rn / 64, Tn), 128>>>(inp, win, bias);
    for (int t = 0; t < Tn; t++) {
        step_hmma_kernel<<<dim3(KSPLIT, NRT), 256>>>(lengths, out, t);
    }
}

// round 13
// speedup vs baseline: 2.7616x; 1.1207x over previous
#include <cuda_runtime.h>
#include <cuda_bf16.h>
#include <cstdint>

#define Tn 256
#define Bn 64
#define Dn 768
#define Rn 2048

#define KSPLIT 8
#define KCTA   (Rn / KSPLIT)   // 256
#define MCTA   64              // rows per CTA
#define NRT    (Rn / MCTA)     // 32 r-tiles
#define KCH    32              // k per chunk
#define NCHUNK (KCTA / KCH)    // 8
#define STRIDE 40              // bf16 elems per smem row (32 + 8 pad) -> conflict-free frags
#define PLANE  (64 * STRIDE * 2)   // 5120 B per plane
#define BUFSZ  (4 * PLANE)         // 20480 B per buffer (Whi,Wlo,Xhi,Xlo)

// Scratch (static __device__ arrays: allocation-guard safe)
__device__ float g_P[(size_t)Tn * Rn * Bn];            // [t][r][b] proj + bias
__device__ uint4 g_Whi4[(size_t)Rn * Rn / 8];          // bf16 W_hi [r][k]
__device__ uint4 g_Wlo4[(size_t)Rn * Rn / 8];          // bf16 W_lo [r][k]
__device__ uint4 g_xh4[2][(size_t)Bn * Rn / 8];        // bf16 x_hi [b][r] ping-pong
__device__ uint4 g_xl4[2][(size_t)Bn * Rn / 8];        // bf16 x_lo [b][r] ping-pong

// ---- packed f32x2 helpers (proj kernel) ----
__device__ __forceinline__ void ffma2(unsigned long long& d, unsigned long long a, unsigned long long b) {
    asm("fma.rn.f32x2 %0, %1, %2, %0;" : "+l"(d) : "l"(a), "l"(b));
}
__device__ __forceinline__ unsigned long long pack2(float lo, float hi) {
    unsigned long long r;
    asm("mov.b64 %0, {%1, %2};" : "=l"(r) : "f"(lo), "f"(hi));
    return r;
}
__device__ __forceinline__ void unpack2(unsigned long long v, float& lo, float& hi) {
    asm("mov.b64 {%0, %1}, %2;" : "=f"(lo), "=f"(hi) : "l"(v));
}

// ---- cluster / DSMEM helpers (R8-proven) ----
__device__ __forceinline__ uint32_t smem_u32(const void* p) {
    uint32_t a;
    asm("{ .reg .u64 t; cvta.to.shared.u64 t, %1; cvt.u32.u64 %0, t; }" : "=r"(a) : "l"(p));
    return a;
}
__device__ __forceinline__ uint32_t mapa_cluster(uint32_t local_addr, uint32_t rank) {
    uint32_t r;
    asm("mapa.shared::cluster.u32 %0, %1, %2;" : "=r"(r) : "r"(local_addr), "r"(rank));
    return r;
}
__device__ __forceinline__ float ld_dsmem_f32(uint32_t addr) {
    float v;
    asm volatile("ld.shared::cluster.f32 %0, [%1];" : "=f"(v) : "r"(addr));
    return v;
}
#define CLUSTER_ARRIVE() asm volatile("barrier.cluster.arrive.aligned;" ::: "memory")
#define CLUSTER_WAIT()   asm volatile("barrier.cluster.wait.aligned;" ::: "memory")

// accurate tanh independent of fast-math flags (~1e-6 rel)
__device__ __forceinline__ float tanh_acc(float x) {
    float ax = fabsf(x);
    float e  = __expf(-2.0f * ax);
    float r  = (1.0f - e) / (1.0f + e);
    return copysignf(r, x);
}

// m16n8k16 row.col bf16 MMA, fp32 accumulate in-place
__device__ __forceinline__ void mma16816(float* d, uint32_t a0, uint32_t a1, uint32_t a2, uint32_t a3,
                                         uint32_t b0, uint32_t b1) {
    asm volatile(
        "mma.sync.aligned.m16n8k16.row.col.f32.bf16.bf16.f32 "
        "{%0,%1,%2,%3}, {%4,%5,%6,%7}, {%8,%9}, {%0,%1,%2,%3};"
        : "+f"(d[0]), "+f"(d[1]), "+f"(d[2]), "+f"(d[3])
        : "r"(a0), "r"(a1), "r"(a2), "r"(a3), "r"(b0), "r"(b1));
}

// ---------------------------------------------------------------------------
// prep: split W into bf16 hi/lo (deterministic, runs every replay)
// ---------------------------------------------------------------------------
__global__ void prep_w_kernel(const float* __restrict__ w) {
    size_t i = (size_t)blockIdx.x * blockDim.x + threadIdx.x;   // one uint4 (8 bf16)
    if (i >= (size_t)Rn * Rn / 8) return;
    const float4* w4 = (const float4*)w;
    float4 f0 = w4[i * 2], f1 = w4[i * 2 + 1];
    float f[8] = {f0.x, f0.y, f0.z, f0.w, f1.x, f1.y, f1.z, f1.w};
    union { __nv_bfloat16 h[8]; uint4 v; } hi, lo;
#pragma unroll
    for (int j = 0; j < 8; j++) {
        hi.h[j] = __float2bfloat16(f[j]);
        lo.h[j] = __float2bfloat16(f[j] - __bfloat162float(hi.h[j]));
    }
    g_Whi4[i] = hi.v;
    g_Wlo4[i] = lo.v;
}

// ---------------------------------------------------------------------------
// init: x_hi/x_lo parity-0 buffers from initial_state
// ---------------------------------------------------------------------------
__global__ void init_x_kernel(const float* __restrict__ init_state) {
    int i = blockIdx.x * blockDim.x + threadIdx.x;   // b*Rn + r
    if (i < Bn * Rn) {
        float v = init_state[i & (Rn - 1)];
        __nv_bfloat16 h = __float2bfloat16(v);
        ((__nv_bfloat16*)g_xh4[0])[i] = h;
        ((__nv_bfloat16*)g_xl4[0])[i] = __float2bfloat16(v - __bfloat162float(h));
    }
}

// ---------------------------------------------------------------------------
// proj (unchanged, fp32): g_P[t][r][b] = inp[t,b,:]·Win[r,:] + bias[r]
// ---------------------------------------------------------------------------
__global__ __launch_bounds__(128) void proj_kernel(const float* __restrict__ inp,
                                                   const float* __restrict__ win,
                                                   const float* __restrict__ bias) {
    __shared__ __align__(16) float As[16][64];
    __shared__ __align__(16) float Bs[16][64];
    const int t  = blockIdx.y;
    const int rt = blockIdx.x;
    const int tid = threadIdx.x;
    const int tx = tid & 15;
    const int ty = tid >> 4;

    unsigned long long acc[4][4];
#pragma unroll
    for (int i = 0; i < 4; i++)
#pragma unroll
        for (int j = 0; j < 4; j++) acc[i][j] = 0ULL;

    const int lrow = tid >> 1;
    const int lcol = (tid & 1) * 8;
    const float* Ap = inp + (size_t)t * Bn * Dn + (size_t)lrow * Dn + lcol;
    const float* Bp = win + (size_t)rt * 64 * Dn + (size_t)lrow * Dn + lcol;

    for (int kk = 0; kk < Dn; kk += 16) {
        float4 a0 = *(const float4*)(Ap + kk);
        float4 a1 = *(const float4*)(Ap + kk + 4);
        float4 b0 = *(const float4*)(Bp + kk);
        float4 b1 = *(const float4*)(Bp + kk + 4);
        __syncthreads();
        As[lcol + 0][lrow] = a0.x; As[lcol + 1][lrow] = a0.y;
        As[lcol + 2][lrow] = a0.z; As[lcol + 3][lrow] = a0.w;
        As[lcol + 4][lrow] = a1.x; As[lcol + 5][lrow] = a1.y;
        As[lcol + 6][lrow] = a1.z; As[lcol + 7][lrow] = a1.w;
        Bs[lcol + 0][lrow] = b0.x; Bs[lcol + 1][lrow] = b0.y;
        Bs[lcol + 2][lrow] = b0.z; Bs[lcol + 3][lrow] = b0.w;
        Bs[lcol + 4][lrow] = b1.x; Bs[lcol + 5][lrow] = b1.y;
        Bs[lcol + 6][lrow] = b1.z; Bs[lcol + 7][lrow] = b1.w;
        __syncthreads();
#pragma unroll
        for (int k = 0; k < 16; k++) {
            float4 av = *(const float4*)&As[k][tx * 4];
            unsigned long long ad0 = pack2(av.x, av.x);
            unsigned long long ad1 = pack2(av.y, av.y);
            unsigned long long ad2 = pack2(av.z, av.z);
            unsigned long long ad3 = pack2(av.w, av.w);
            ulonglong2 w0 = *(const ulonglong2*)&Bs[k][ty * 8];
            ulonglong2 w1 = *(const ulonglong2*)&Bs[k][ty * 8 + 4];
            ffma2(acc[0][0], ad0, w0.x); ffma2(acc[0][1], ad0, w0.y);
            ffma2(acc[0][2], ad0, w1.x); ffma2(acc[0][3], ad0, w1.y);
            ffma2(acc[1][0], ad1, w0.x); ffma2(acc[1][1], ad1, w0.y);
            ffma2(acc[1][2], ad1, w1.x); ffma2(acc[1][3], ad1, w1.y);
            ffma2(acc[2][0], ad2, w0.x); ffma2(acc[2][1], ad2, w0.y);
            ffma2(acc[2][2], ad2, w1.x); ffma2(acc[2][3], ad2, w1.y);
            ffma2(acc[3][0], ad3, w0.x); ffma2(acc[3][1], ad3, w0.y);
            ffma2(acc[3][2], ad3, w1.x); ffma2(acc[3][3], ad3, w1.y);
        }
    }

    float c[4][8];
#pragma unroll
    for (int bb = 0; bb < 4; bb++)
#pragma unroll
        for (int rp = 0; rp < 4; rp++) {
            float lo, hi;
            unpack2(acc[bb][rp], lo, hi);
            c[bb][rp * 2] = lo;
            c[bb][rp * 2 + 1] = hi;
        }
#pragma unroll
    for (int j = 0; j < 8; j++) {
        int r = rt * 64 + ty * 8 + j;
        float bv = bias[r];
        float4 o = make_float4(c[0][j] + bv, c[1][j] + bv, c[2][j] + bv, c[3][j] + bv);
        *(float4*)&g_P[((size_t)t * Rn + r) * Bn + tx * 4] = o;
    }
}

// ---------------------------------------------------------------------------
// step: HMMA split-bf16 recurrence GEMM, cluster(8) k-split, DSMEM reduce.
// grid (KSPLIT=8, NRT=32) = 256 CTAs, block 256 -> 2 CTAs/SM, 16 warps/SM
// (R11 had 128 CTAs = 1 CTA/SM; occupancy was the binding constraint).
// D = Whi*xhi + Whi*xlo + Wlo*xhi, fp32 accum in registers, K=256 per CTA.
// ---------------------------------------------------------------------------
__global__ __launch_bounds__(256) __cluster_dims__(KSPLIT, 1, 1)
void step_hmma_kernel(const int* __restrict__ lengths,
                      float* __restrict__ out,
                      int t) {
    __shared__ __align__(16) char sAll[2 * BUFSZ];   // 40960 B
    const int ks  = blockIdx.x;   // cluster rank = k-slice
    const int rt  = blockIdx.y;
    const int tid = threadIdx.x;
    const int wid = tid >> 5, lane = tid & 31;
    const int g = lane >> 2, tig = lane & 3;
    const int mt = wid & 3, nh = wid >> 2;
    const int r0 = rt * MCTA, k0 = ks * KCTA;

    const __nv_bfloat16* Wh  = (const __nv_bfloat16*)g_Whi4;
    const __nv_bfloat16* Wl  = (const __nv_bfloat16*)g_Wlo4;
    const __nv_bfloat16* xhs = (const __nv_bfloat16*)g_xh4[t & 1];
    const __nv_bfloat16* xls = (const __nv_bfloat16*)g_xl4[t & 1];
    __nv_bfloat16* xhd = (__nv_bfloat16*)g_xh4[(t & 1) ^ 1];
    __nv_bfloat16* xld = (__nv_bfloat16*)g_xl4[(t & 1) ^ 1];

    float d[4][4];
#pragma unroll
    for (int i = 0; i < 4; i++)
#pragma unroll
        for (int j = 0; j < 4; j++) d[i][j] = 0.0f;

    // staging: one uint4 per thread per plane per chunk (64 rows x 4 uint4)
    const int srow = tid >> 2;
    const int sc4  = tid & 3;
    const int soff = srow * (STRIDE * 2) + sc4 * 16;   // bytes within plane

    uint4 vwh, vwl, vxh, vxl;
    {
        const int kk = k0 + sc4 * 8;
        vwh = *(const uint4*)(Wh + (size_t)(r0 + srow) * Rn + kk);
        vwl = *(const uint4*)(Wl + (size_t)(r0 + srow) * Rn + kk);
        vxh = *(const uint4*)(xhs + (size_t)srow * Rn + kk);
        vxl = *(const uint4*)(xls + (size_t)srow * Rn + kk);
    }

    const int ar0 = (mt * 16 + g) * (STRIDE * 2);
    const int ar1 = (mt * 16 + g + 8) * (STRIDE * 2);

    for (int c = 0; c < NCHUNK; c++) {
        char* buf = sAll + (c & 1) * BUFSZ;
        __syncthreads();
        *(uint4*)(buf + 0 * PLANE + soff) = vwh;
        *(uint4*)(buf + 1 * PLANE + soff) = vwl;
        *(uint4*)(buf + 2 * PLANE + soff) = vxh;
        *(uint4*)(buf + 3 * PLANE + soff) = vxl;
        __syncthreads();
        if (c + 1 < NCHUNK) {
            const int kk = k0 + (c + 1) * KCH + sc4 * 8;
            vwh = *(const uint4*)(Wh + (size_t)(r0 + srow) * Rn + kk);
            vwl = *(const uint4*)(Wl + (size_t)(r0 + srow) * Rn + kk);
            vxh = *(const uint4*)(xhs + (size_t)srow * Rn + kk);
            vxl = *(const uint4*)(xls + (size_t)srow * Rn + kk);
        }
        const char* AH = buf;
        const char* AL = buf + PLANE;
        const char* BH = buf + 2 * PLANE;
        const char* BL = buf + 3 * PLANE;
#pragma unroll
        for (int ki = 0; ki < KCH / 16; ki++) {
            const int acol = (ki * 16 + 2 * tig) * 2;   // bytes
            uint32_t ah0 = *(const uint32_t*)(AH + ar0 + acol);
            uint32_t ah1 = *(const uint32_t*)(AH + ar1 + acol);
            uint32_t ah2 = *(const uint32_t*)(AH + ar0 + acol + 16);
            uint32_t ah3 = *(const uint32_t*)(AH + ar1 + acol + 16);
            uint32_t al0 = *(const uint32_t*)(AL + ar0 + acol);
            uint32_t al1 = *(const uint32_t*)(AL + ar1 + acol);
            uint32_t al2 = *(const uint32_t*)(AL + ar0 + acol + 16);
            uint32_t al3 = *(const uint32_t*)(AL + ar1 + acol + 16);
#pragma unroll
            for (int nt = 0; nt < 4; nt++) {
                const int brow = (nh * 32 + nt * 8 + g) * (STRIDE * 2);
                uint32_t bh0 = *(const uint32_t*)(BH + brow + acol);
                uint32_t bh1 = *(const uint32_t*)(BH + brow + acol + 16);
                uint32_t bl0 = *(const uint32_t*)(BL + brow + acol);
                uint32_t bl1 = *(const uint32_t*)(BL + brow + acol + 16);
                mma16816(d[nt], ah0, ah1, ah2, ah3, bh0, bh1);   // Whi*xhi
                mma16816(d[nt], ah0, ah1, ah2, ah3, bl0, bl1);   // Whi*xlo
                mma16816(d[nt], al0, al1, al2, al3, bh0, bh1);   // Wlo*xhi
            }
        }
    }

    // partial [64r][64n] fp32 at sAll[0..16384)
    float* part = (float*)sAll;
#pragma unroll
    for (int nt = 0; nt < 4; nt++) {
        const int n = nh * 32 + nt * 8 + 2 * tig;
        const int r = mt * 16 + g;
        *(float2*)&part[r * 64 + n]       = make_float2(d[nt][0], d[nt][1]);
        *(float2*)&part[(r + 8) * 64 + n] = make_float2(d[nt][2], d[nt][3]);
    }
    __syncthreads();   // partial complete (release)
    CLUSTER_ARRIVE();  // barrier #1: my partial is published

    // prefetch epilogue operands behind arrival skew.
    // This CTA reduces rows [r0 + ks*8, +8): 512 values, 2 consecutive r per thread.
    const int b    = tid & 63;
    const int rloc = ks * 8 + (tid >> 6) * 2;
    const int r    = r0 + rloc;
    float pv[2], xo[2];
#pragma unroll
    for (int j = 0; j < 2; j++) {
        pv[j] = g_P[((size_t)t * Rn + r + j) * Bn + b];
        xo[j] = __bfloat162float(xhs[(size_t)b * Rn + r + j])
              + __bfloat162float(xls[(size_t)b * Rn + r + j]);
    }
    const int len = lengths[b];

    CLUSTER_WAIT();    // barrier #1 wait: all partials visible

    const uint32_t pbase = smem_u32(sAll);
    float pr[KSPLIT][2];
#pragma unroll
    for (int peer = 0; peer < KSPLIT; peer++) {
#pragma unroll
        for (int j = 0; j < 2; j++) {
            uint32_t addr = mapa_cluster(pbase + (uint32_t)((rloc + j) * 64 + b) * 4u, (uint32_t)peer);
            pr[peer][j] = ld_dsmem_f32(addr);
        }
    }

    CLUSTER_ARRIVE();  // barrier #2: done reading peer SMEM

    const float m = (len > t) ? 0.5f : 0.0f;   // mask * lr (lr = 1-lr = 0.5)
    float2 ov;
#pragma unroll
    for (int j = 0; j < 2; j++) {
        float sum = pv[j];
#pragma unroll
        for (int peer = 0; peer < KSPLIT; peer++) sum += pr[peer][j];   // fixed order
        const float xn = m * (xo[j] + tanh_acc(sum));
        ((float*)&ov)[j] = xn;
        const __nv_bfloat16 h = __float2bfloat16(xn);
        xhd[(size_t)b * Rn + r + j] = h;
        xld[(size_t)b * Rn + r + j] = __float2bfloat16(xn - __bfloat162float(h));
    }
    *(float2*)&out[((size_t)b * Tn + t) * Rn + r] = ov;

    CLUSTER_WAIT();    // barrier #2 wait: safe to exit
}

// ---------------------------------------------------------------------------
// launch: prep + init + proj + 256 HMMA step kernels — all graph-capturable
// ---------------------------------------------------------------------------
extern "C" void kernel_launch(void* const* d_in, const int* in_sizes, int n_in,
                              void* d_out, int out_size) {
    const float* inp     = (const float*)d_in[0];  // [T,B,D]
    const int*   lengths = (const int*)d_in[1];    // [B]
    const float* win     = (const float*)d_in[2];  // [R,D]
    const float* wres    = (const float*)d_in[3];  // [R,R]
    const float* bias    = (const float*)d_in[4];  // [R]
    const float* x0in    = (const float*)d_in[5];  // [R]
    float* out = (float*)d_out;                    // [B,T,R]

    prep_w_kernel<<<(Rn * Rn / 8 + 255) / 256, 256>>>(wres);
    init_x_kernel<<<(Bn * Rn + 255) / 256, 256>>>(x0in);
    proj_kernel<<<dim3(Rn / 64, Tn), 128>>>(inp, win, bias);
    for (int t = 0; t < Tn; t++) {
        step_hmma_kernel<<<dim3(KSPLIT, NRT), 256>>>(lengths, out, t);
    }
}

// round 14
// speedup vs baseline: 2.8556x; 1.0340x over previous
#include <cuda_runtime.h>
#include <cuda_bf16.h>
#include <cstdint>

#define Tn 256
#define Bn 64
#define Dn 768
#define Rn 2048

#define KSPLIT 8
#define KCTA   (Rn / KSPLIT)   // 256
#define MCTA   64              // rows per CTA
#define NRT    (Rn / MCTA)     // 32 r-tiles
#define KCH    32              // k per chunk
#define NCHUNK (KCTA / KCH)    // 8
#define STRIDE 40              // bf16 elems per smem row (32 + 8 pad) -> conflict-free frags
#define PLANE  (64 * STRIDE * 2)   // 5120 B per plane
#define BUFSZ  (4 * PLANE)         // 20480 B per stage (Whi,Wlo,Xhi,Xlo)
#define NSTAGE 4
#define SMEM_DYN (NSTAGE * BUFSZ)  // 81920 B

// Scratch (static __device__ arrays: allocation-guard safe)
__device__ float g_P[(size_t)Tn * Rn * Bn];            // [t][r][b] proj + bias
__device__ uint4 g_Whi4[(size_t)Rn * Rn / 8];          // bf16 W_hi [r][k]
__device__ uint4 g_Wlo4[(size_t)Rn * Rn / 8];          // bf16 W_lo [r][k]
__device__ uint4 g_xh4[2][(size_t)Bn * Rn / 8];        // bf16 x_hi [b][r] ping-pong
__device__ uint4 g_xl4[2][(size_t)Bn * Rn / 8];        // bf16 x_lo [b][r] ping-pong

// ---- packed f32x2 helpers (proj kernel) ----
__device__ __forceinline__ void ffma2(unsigned long long& d, unsigned long long a, unsigned long long b) {
    asm("fma.rn.f32x2 %0, %1, %2, %0;" : "+l"(d) : "l"(a), "l"(b));
}
__device__ __forceinline__ unsigned long long pack2(float lo, float hi) {
    unsigned long long r;
    asm("mov.b64 %0, {%1, %2};" : "=l"(r) : "f"(lo), "f"(hi));
    return r;
}
__device__ __forceinline__ void unpack2(unsigned long long v, float& lo, float& hi) {
    asm("mov.b64 {%0, %1}, %2;" : "=f"(lo), "=f"(hi) : "l"(v));
}

// ---- cluster / DSMEM helpers (R8-proven) ----
__device__ __forceinline__ uint32_t smem_u32(const void* p) {
    uint32_t a;
    asm("{ .reg .u64 t; cvta.to.shared.u64 t, %1; cvt.u32.u64 %0, t; }" : "=r"(a) : "l"(p));
    return a;
}
__device__ __forceinline__ uint32_t mapa_cluster(uint32_t local_addr, uint32_t rank) {
    uint32_t r;
    asm("mapa.shared::cluster.u32 %0, %1, %2;" : "=r"(r) : "r"(local_addr), "r"(rank));
    return r;
}
__device__ __forceinline__ float ld_dsmem_f32(uint32_t addr) {
    float v;
    asm volatile("ld.shared::cluster.f32 %0, [%1];" : "=f"(v) : "r"(addr));
    return v;
}
#define CLUSTER_ARRIVE() asm volatile("barrier.cluster.arrive.aligned;" ::: "memory")
#define CLUSTER_WAIT()   asm volatile("barrier.cluster.wait.aligned;" ::: "memory")

// ---- cp.async helpers ----
__device__ __forceinline__ void cp16(uint32_t smem_addr, const void* gptr) {
    asm volatile("cp.async.cg.shared.global [%0], [%1], 16;" :: "r"(smem_addr), "l"(gptr));
}
#define CP_COMMIT() asm volatile("cp.async.commit_group;" ::: "memory")
#define CP_WAIT(n)  asm volatile("cp.async.wait_group %0;" :: "n"(n) : "memory")

// accurate tanh independent of fast-math flags (~1e-6 rel)
__device__ __forceinline__ float tanh_acc(float x) {
    float ax = fabsf(x);
    float e  = __expf(-2.0f * ax);
    float r  = (1.0f - e) / (1.0f + e);
    return copysignf(r, x);
}

// m16n8k16 row.col bf16 MMA, fp32 accumulate in-place
__device__ __forceinline__ void mma16816(float* d, uint32_t a0, uint32_t a1, uint32_t a2, uint32_t a3,
                                         uint32_t b0, uint32_t b1) {
    asm volatile(
        "mma.sync.aligned.m16n8k16.row.col.f32.bf16.bf16.f32 "
        "{%0,%1,%2,%3}, {%4,%5,%6,%7}, {%8,%9}, {%0,%1,%2,%3};"
        : "+f"(d[0]), "+f"(d[1]), "+f"(d[2]), "+f"(d[3])
        : "r"(a0), "r"(a1), "r"(a2), "r"(a3), "r"(b0), "r"(b1));
}

// ---------------------------------------------------------------------------
// prep: split W into bf16 hi/lo (deterministic, runs every replay)
// ---------------------------------------------------------------------------
__global__ void prep_w_kernel(const float* __restrict__ w) {
    size_t i = (size_t)blockIdx.x * blockDim.x + threadIdx.x;   // one uint4 (8 bf16)
    if (i >= (size_t)Rn * Rn / 8) return;
    const float4* w4 = (const float4*)w;
    float4 f0 = w4[i * 2], f1 = w4[i * 2 + 1];
    float f[8] = {f0.x, f0.y, f0.z, f0.w, f1.x, f1.y, f1.z, f1.w};
    union { __nv_bfloat16 h[8]; uint4 v; } hi, lo;
#pragma unroll
    for (int j = 0; j < 8; j++) {
        hi.h[j] = __float2bfloat16(f[j]);
        lo.h[j] = __float2bfloat16(f[j] - __bfloat162float(hi.h[j]));
    }
    g_Whi4[i] = hi.v;
    g_Wlo4[i] = lo.v;
}

// ---------------------------------------------------------------------------
// init: x_hi/x_lo parity-0 buffers from initial_state
// ---------------------------------------------------------------------------
__global__ void init_x_kernel(const float* __restrict__ init_state) {
    int i = blockIdx.x * blockDim.x + threadIdx.x;   // b*Rn + r
    if (i < Bn * Rn) {
        float v = init_state[i & (Rn - 1)];
        __nv_bfloat16 h = __float2bfloat16(v);
        ((__nv_bfloat16*)g_xh4[0])[i] = h;
        ((__nv_bfloat16*)g_xl4[0])[i] = __float2bfloat16(v - __bfloat162float(h));
    }
}

// ---------------------------------------------------------------------------
// proj (unchanged, fp32): g_P[t][r][b] = inp[t,b,:]·Win[r,:] + bias[r]
// ---------------------------------------------------------------------------
__global__ __launch_bounds__(128) void proj_kernel(const float* __restrict__ inp,
                                                   const float* __restrict__ win,
                                                   const float* __restrict__ bias) {
    __shared__ __align__(16) float As[16][64];
    __shared__ __align__(16) float Bs[16][64];
    const int t  = blockIdx.y;
    const int rt = blockIdx.x;
    const int tid = threadIdx.x;
    const int tx = tid & 15;
    const int ty = tid >> 4;

    unsigned long long acc[4][4];
#pragma unroll
    for (int i = 0; i < 4; i++)
#pragma unroll
        for (int j = 0; j < 4; j++) acc[i][j] = 0ULL;

    const int lrow = tid >> 1;
    const int lcol = (tid & 1) * 8;
    const float* Ap = inp + (size_t)t * Bn * Dn + (size_t)lrow * Dn + lcol;
    const float* Bp = win + (size_t)rt * 64 * Dn + (size_t)lrow * Dn + lcol;

    for (int kk = 0; kk < Dn; kk += 16) {
        float4 a0 = *(const float4*)(Ap + kk);
        float4 a1 = *(const float4*)(Ap + kk + 4);
        float4 b0 = *(const float4*)(Bp + kk);
        float4 b1 = *(const float4*)(Bp + kk + 4);
        __syncthreads();
        As[lcol + 0][lrow] = a0.x; As[lcol + 1][lrow] = a0.y;
        As[lcol + 2][lrow] = a0.z; As[lcol + 3][lrow] = a0.w;
        As[lcol + 4][lrow] = a1.x; As[lcol + 5][lrow] = a1.y;
        As[lcol + 6][lrow] = a1.z; As[lcol + 7][lrow] = a1.w;
        Bs[lcol + 0][lrow] = b0.x; Bs[lcol + 1][lrow] = b0.y;
        Bs[lcol + 2][lrow] = b0.z; Bs[lcol + 3][lrow] = b0.w;
        Bs[lcol + 4][lrow] = b1.x; Bs[lcol + 5][lrow] = b1.y;
        Bs[lcol + 6][lrow] = b1.z; Bs[lcol + 7][lrow] = b1.w;
        __syncthreads();
#pragma unroll
        for (int k = 0; k < 16; k++) {
            float4 av = *(const float4*)&As[k][tx * 4];
            unsigned long long ad0 = pack2(av.x, av.x);
            unsigned long long ad1 = pack2(av.y, av.y);
            unsigned long long ad2 = pack2(av.z, av.z);
            unsigned long long ad3 = pack2(av.w, av.w);
            ulonglong2 w0 = *(const ulonglong2*)&Bs[k][ty * 8];
            ulonglong2 w1 = *(const ulonglong2*)&Bs[k][ty * 8 + 4];
            ffma2(acc[0][0], ad0, w0.x); ffma2(acc[0][1], ad0, w0.y);
            ffma2(acc[0][2], ad0, w1.x); ffma2(acc[0][3], ad0, w1.y);
            ffma2(acc[1][0], ad1, w0.x); ffma2(acc[1][1], ad1, w0.y);
            ffma2(acc[1][2], ad1, w1.x); ffma2(acc[1][3], ad1, w1.y);
            ffma2(acc[2][0], ad2, w0.x); ffma2(acc[2][1], ad2, w0.y);
            ffma2(acc[2][2], ad2, w1.x); ffma2(acc[2][3], ad2, w1.y);
            ffma2(acc[3][0], ad3, w0.x); ffma2(acc[3][1], ad3, w0.y);
            ffma2(acc[3][2], ad3, w1.x); ffma2(acc[3][3], ad3, w1.y);
        }
    }

    float c[4][8];
#pragma unroll
    for (int bb = 0; bb < 4; bb++)
#pragma unroll
        for (int rp = 0; rp < 4; rp++) {
            float lo, hi;
            unpack2(acc[bb][rp], lo, hi);
            c[bb][rp * 2] = lo;
            c[bb][rp * 2 + 1] = hi;
        }
#pragma unroll
    for (int j = 0; j < 8; j++) {
        int r = rt * 64 + ty * 8 + j;
        float bv = bias[r];
        float4 o = make_float4(c[0][j] + bv, c[1][j] + bv, c[2][j] + bv, c[3][j] + bv);
        *(float4*)&g_P[((size_t)t * Rn + r) * Bn + tx * 4] = o;
    }
}

// ---------------------------------------------------------------------------
// step: HMMA split-bf16 recurrence GEMM, cluster(8) k-split, DSMEM reduce,
// 4-stage cp.async pipeline (3 chunks in flight -> staging latency hidden).
// grid (8, 32) = 256 CTAs, block 256, 82KB dynamic smem (2 CTAs/SM).
// ---------------------------------------------------------------------------
__global__ __launch_bounds__(256) __cluster_dims__(KSPLIT, 1, 1)
void step_hmma_kernel(const int* __restrict__ lengths,
                      float* __restrict__ out,
                      int t) {
    extern __shared__ __align__(16) char sAll[];     // NSTAGE * BUFSZ
    const int ks  = blockIdx.x;   // cluster rank = k-slice
    const int rt  = blockIdx.y;
    const int tid = threadIdx.x;
    const int wid = tid >> 5, lane = tid & 31;
    const int g = lane >> 2, tig = lane & 3;
    const int mt = wid & 3, nh = wid >> 2;
    const int r0 = rt * MCTA, k0 = ks * KCTA;

    const __nv_bfloat16* Wh  = (const __nv_bfloat16*)g_Whi4;
    const __nv_bfloat16* Wl  = (const __nv_bfloat16*)g_Wlo4;
    const __nv_bfloat16* xhs = (const __nv_bfloat16*)g_xh4[t & 1];
    const __nv_bfloat16* xls = (const __nv_bfloat16*)g_xl4[t & 1];
    __nv_bfloat16* xhd = (__nv_bfloat16*)g_xh4[(t & 1) ^ 1];
    __nv_bfloat16* xld = (__nv_bfloat16*)g_xl4[(t & 1) ^ 1];

    float d[4][4];
#pragma unroll
    for (int i = 0; i < 4; i++)
#pragma unroll
        for (int j = 0; j < 4; j++) d[i][j] = 0.0f;

    // staging map: one uint4 per thread per plane per chunk
    const int srow = tid >> 2;
    const int sc4  = tid & 3;
    const uint32_t soff = (uint32_t)(srow * (STRIDE * 2) + sc4 * 16);
    const uint32_t sb = smem_u32(sAll);

    auto issue = [&](int c) {
        const uint32_t base = sb + (uint32_t)((c & (NSTAGE - 1)) * BUFSZ);
        const int kk = k0 + c * KCH + sc4 * 8;
        cp16(base + 0 * PLANE + soff, Wh  + (size_t)(r0 + srow) * Rn + kk);
        cp16(base + 1 * PLANE + soff, Wl  + (size_t)(r0 + srow) * Rn + kk);
        cp16(base + 2 * PLANE + soff, xhs + (size_t)srow * Rn + kk);
        cp16(base + 3 * PLANE + soff, xls + (size_t)srow * Rn + kk);
        CP_COMMIT();
    };

    issue(0); issue(1); issue(2);

    const int ar0 = (mt * 16 + g) * (STRIDE * 2);
    const int ar1 = (mt * 16 + g + 8) * (STRIDE * 2);

    for (int c = 0; c < NCHUNK; c++) {
        if (c + 3 < NCHUNK) CP_WAIT(2); else CP_WAIT(0);
        __syncthreads();
        if (c + 3 < NCHUNK) issue(c + 3);
        const char* buf = sAll + (c & (NSTAGE - 1)) * BUFSZ;
        const char* AH = buf;
        const char* AL = buf + PLANE;
        const char* BH = buf + 2 * PLANE;
        const char* BL = buf + 3 * PLANE;
#pragma unroll
        for (int ki = 0; ki < KCH / 16; ki++) {
            const int acol = (ki * 16 + 2 * tig) * 2;   // bytes
            uint32_t ah0 = *(const uint32_t*)(AH + ar0 + acol);
            uint32_t ah1 = *(const uint32_t*)(AH + ar1 + acol);
            uint32_t ah2 = *(const uint32_t*)(AH + ar0 + acol + 16);
            uint32_t ah3 = *(const uint32_t*)(AH + ar1 + acol + 16);
            uint32_t al0 = *(const uint32_t*)(AL + ar0 + acol);
            uint32_t al1 = *(const uint32_t*)(AL + ar1 + acol);
            uint32_t al2 = *(const uint32_t*)(AL + ar0 + acol + 16);
            uint32_t al3 = *(const uint32_t*)(AL + ar1 + acol + 16);
#pragma unroll
            for (int nt = 0; nt < 4; nt++) {
                const int brow = (nh * 32 + nt * 8 + g) * (STRIDE * 2);
                uint32_t bh0 = *(const uint32_t*)(BH + brow + acol);
                uint32_t bh1 = *(const uint32_t*)(BH + brow + acol + 16);
                uint32_t bl0 = *(const uint32_t*)(BL + brow + acol);
                uint32_t bl1 = *(const uint32_t*)(BL + brow + acol + 16);
                mma16816(d[nt], ah0, ah1, ah2, ah3, bh0, bh1);   // Whi*xhi
                mma16816(d[nt], ah0, ah1, ah2, ah3, bl0, bl1);   // Whi*xlo
                mma16816(d[nt], al0, al1, al2, al3, bh0, bh1);   // Wlo*xhi
            }
        }
        __syncthreads();   // stage consumed before refill (ring distance = NSTAGE)
    }

    // partial [64r][64n] fp32 at sAll[0..16384)
    float* part = (float*)sAll;
#pragma unroll
    for (int nt = 0; nt < 4; nt++) {
        const int n = nh * 32 + nt * 8 + 2 * tig;
        const int r = mt * 16 + g;
        *(float2*)&part[r * 64 + n]       = make_float2(d[nt][0], d[nt][1]);
        *(float2*)&part[(r + 8) * 64 + n] = make_float2(d[nt][2], d[nt][3]);
    }
    __syncthreads();   // partial complete (release)
    CLUSTER_ARRIVE();  // barrier #1: my partial is published

    // prefetch epilogue operands behind arrival skew.
    // This CTA reduces rows [r0 + ks*8, +8): 512 values, 2 consecutive r per thread.
    const int b    = tid & 63;
    const int rloc = ks * 8 + (tid >> 6) * 2;
    const int r    = r0 + rloc;
    float pv[2], xo[2];
#pragma unroll
    for (int j = 0; j < 2; j++) {
        pv[j] = g_P[((size_t)t * Rn + r + j) * Bn + b];
        xo[j] = __bfloat162float(xhs[(size_t)b * Rn + r + j])
              + __bfloat162float(xls[(size_t)b * Rn + r + j]);
    }
    const int len = lengths[b];

    CLUSTER_WAIT();    // barrier #1 wait: all partials visible

    const uint32_t pbase = sb;
    float pr[KSPLIT][2];
#pragma unroll
    for (int peer = 0; peer < KSPLIT; peer++) {
#pragma unroll
        for (int j = 0; j < 2; j++) {
            uint32_t addr = mapa_cluster(pbase + (uint32_t)((rloc + j) * 64 + b) * 4u, (uint32_t)peer);
            pr[peer][j] = ld_dsmem_f32(addr);
        }
    }

    CLUSTER_ARRIVE();  // barrier #2: done reading peer SMEM

    const float m = (len > t) ? 0.5f : 0.0f;   // mask * lr (lr = 1-lr = 0.5)
    float2 ov;
#pragma unroll
    for (int j = 0; j < 2; j++) {
        float sum = pv[j];
#pragma unroll
        for (int peer = 0; peer < KSPLIT; peer++) sum += pr[peer][j];   // fixed order
        const float xn = m * (xo[j] + tanh_acc(sum));
        ((float*)&ov)[j] = xn;
        const __nv_bfloat16 h = __float2bfloat16(xn);
        xhd[(size_t)b * Rn + r + j] = h;
        xld[(size_t)b * Rn + r + j] = __float2bfloat16(xn - __bfloat162float(h));
    }
    *(float2*)&out[((size_t)b * Tn + t) * Rn + r] = ov;

    CLUSTER_WAIT();    // barrier #2 wait: safe to exit
}

// ---------------------------------------------------------------------------
// launch: prep + init + proj + 256 HMMA step kernels — all graph-capturable
// ---------------------------------------------------------------------------
extern "C" void kernel_launch(void* const* d_in, const int* in_sizes, int n_in,
                              void* d_out, int out_size) {
    const float* inp     = (const float*)d_in[0];  // [T,B,D]
    const int*   lengths = (const int*)d_in[1];    // [B]
    const float* win     = (const float*)d_in[2];  // [R,D]
    const float* wres    = (const float*)d_in[3];  // [R,R]
    const float* bias    = (const float*)d_in[4];  // [R]
    const float* x0in    = (const float*)d_in[5];  // [R]
    float* out = (float*)d_out;                    // [B,T,R]

    // host-side function attribute; idempotent, not a stream/alloc op
    cudaFuncSetAttribute(step_hmma_kernel, cudaFuncAttributeMaxDynamicSharedMemorySize, SMEM_DYN);

    prep_w_kernel<<<(Rn * Rn / 8 + 255) / 256, 256>>>(wres);
    init_x_kernel<<<(Bn * Rn + 255) / 256, 256>>>(x0in);
    proj_kernel<<<dim3(Rn / 64, Tn), 128>>>(inp, win, bias);
    for (int t = 0; t < Tn; t++) {
        step_hmma_kernel<<<dim3(KSPLIT, NRT), 256, SMEM_DYN>>>(lengths, out, t);
    }
}

// round 15
// speedup vs baseline: 2.9786x; 1.0431x over previous
#include <cuda_runtime.h>
#include <cuda_bf16.h>
#include <cstdint>

#define Tn 256
#define Bn 64
#define Dn 768
#define Rn 2048

#define KSPLIT 8
#define KCTA   (Rn / KSPLIT)   // 256
#define MCTA   64              // rows per CTA
#define NRT    (Rn / MCTA)     // 32 r-tiles
#define KCH    32              // k per chunk
#define NCHUNK (KCTA / KCH)    // 8
#define STRIDE 40              // bf16 elems per smem row (32 + 8 pad)
#define ROWB   (STRIDE * 2)    // 80 bytes per row
#define PLANE  (64 * ROWB)     // 5120 B per plane
#define BUFSZ  (4 * PLANE)     // 20480 B per stage (Whi,Wlo,Xhi,Xlo)
#define NSTAGE 4
#define SMEM_DYN (NSTAGE * BUFSZ)  // 81920 B

// Scratch (static __device__ arrays: allocation-guard safe)
__device__ float g_P[(size_t)Tn * Rn * Bn];            // [t][r][b] proj + bias
__device__ uint4 g_Whi4[(size_t)Rn * Rn / 8];          // bf16 W_hi [r][k]
__device__ uint4 g_Wlo4[(size_t)Rn * Rn / 8];          // bf16 W_lo [r][k]
__device__ uint4 g_xh4[2][(size_t)Bn * Rn / 8];        // bf16 x_hi [b][r] ping-pong
__device__ uint4 g_xl4[2][(size_t)Bn * Rn / 8];        // bf16 x_lo [b][r] ping-pong

// ---- packed f32x2 helpers (proj kernel) ----
__device__ __forceinline__ void ffma2(unsigned long long& d, unsigned long long a, unsigned long long b) {
    asm("fma.rn.f32x2 %0, %1, %2, %0;" : "+l"(d) : "l"(a), "l"(b));
}
__device__ __forceinline__ unsigned long long pack2(float lo, float hi) {
    unsigned long long r;
    asm("mov.b64 %0, {%1, %2};" : "=l"(r) : "f"(lo), "f"(hi));
    return r;
}
__device__ __forceinline__ void unpack2(unsigned long long v, float& lo, float& hi) {
    asm("mov.b64 {%0, %1}, %2;" : "=f"(lo), "=f"(hi) : "l"(v));
}

// ---- cluster / DSMEM helpers ----
__device__ __forceinline__ uint32_t smem_u32(const void* p) {
    uint32_t a;
    asm("{ .reg .u64 t; cvta.to.shared.u64 t, %1; cvt.u32.u64 %0, t; }" : "=r"(a) : "l"(p));
    return a;
}
__device__ __forceinline__ uint32_t mapa_cluster(uint32_t local_addr, uint32_t rank) {
    uint32_t r;
    asm("mapa.shared::cluster.u32 %0, %1, %2;" : "=r"(r) : "r"(local_addr), "r"(rank));
    return r;
}
__device__ __forceinline__ float ld_dsmem_f32(uint32_t addr) {
    float v;
    asm volatile("ld.shared::cluster.f32 %0, [%1];" : "=f"(v) : "r"(addr));
    return v;
}
#define CLUSTER_ARRIVE() asm volatile("barrier.cluster.arrive.aligned;" ::: "memory")
#define CLUSTER_WAIT()   asm volatile("barrier.cluster.wait.aligned;" ::: "memory")

// ---- cp.async helpers ----
__device__ __forceinline__ void cp16(uint32_t smem_addr, const void* gptr) {
    asm volatile("cp.async.cg.shared.global [%0], [%1], 16;" :: "r"(smem_addr), "l"(gptr));
}
#define CP_COMMIT() asm volatile("cp.async.commit_group;" ::: "memory")
#define CP_WAIT(n)  asm volatile("cp.async.wait_group %0;" :: "n"(n) : "memory")

// ---- ldmatrix ----
__device__ __forceinline__ void ldsm4(uint32_t& r0, uint32_t& r1, uint32_t& r2, uint32_t& r3,
                                      uint32_t addr) {
    asm volatile("ldmatrix.sync.aligned.m8n8.x4.shared.b16 {%0,%1,%2,%3}, [%4];"
        : "=r"(r0), "=r"(r1), "=r"(r2), "=r"(r3) : "r"(addr));
}

// accurate tanh independent of fast-math flags (~1e-6 rel)
__device__ __forceinline__ float tanh_acc(float x) {
    float ax = fabsf(x);
    float e  = __expf(-2.0f * ax);
    float r  = (1.0f - e) / (1.0f + e);
    return copysignf(r, x);
}

// m16n8k16 row.col bf16 MMA, fp32 accumulate in-place
__device__ __forceinline__ void mma16816(float* d, uint32_t a0, uint32_t a1, uint32_t a2, uint32_t a3,
                                         uint32_t b0, uint32_t b1) {
    asm volatile(
        "mma.sync.aligned.m16n8k16.row.col.f32.bf16.bf16.f32 "
        "{%0,%1,%2,%3}, {%4,%5,%6,%7}, {%8,%9}, {%0,%1,%2,%3};"
        : "+f"(d[0]), "+f"(d[1]), "+f"(d[2]), "+f"(d[3])
        : "r"(a0), "r"(a1), "r"(a2), "r"(a3), "r"(b0), "r"(b1));
}

// ---------------------------------------------------------------------------
// prep: split W into bf16 hi/lo (deterministic, runs every replay)
// ---------------------------------------------------------------------------
__global__ void prep_w_kernel(const float* __restrict__ w) {
    size_t i = (size_t)blockIdx.x * blockDim.x + threadIdx.x;   // one uint4 (8 bf16)
    if (i >= (size_t)Rn * Rn / 8) return;
    const float4* w4 = (const float4*)w;
    float4 f0 = w4[i * 2], f1 = w4[i * 2 + 1];
    float f[8] = {f0.x, f0.y, f0.z, f0.w, f1.x, f1.y, f1.z, f1.w};
    union { __nv_bfloat16 h[8]; uint4 v; } hi, lo;
#pragma unroll
    for (int j = 0; j < 8; j++) {
        hi.h[j] = __float2bfloat16(f[j]);
        lo.h[j] = __float2bfloat16(f[j] - __bfloat162float(hi.h[j]));
    }
    g_Whi4[i] = hi.v;
    g_Wlo4[i] = lo.v;
}

// ---------------------------------------------------------------------------
// init: x_hi/x_lo parity-0 buffers from initial_state
// ---------------------------------------------------------------------------
__global__ void init_x_kernel(const float* __restrict__ init_state) {
    int i = blockIdx.x * blockDim.x + threadIdx.x;   // b*Rn + r
    if (i < Bn * Rn) {
        float v = init_state[i & (Rn - 1)];
        __nv_bfloat16 h = __float2bfloat16(v);
        ((__nv_bfloat16*)g_xh4[0])[i] = h;
        ((__nv_bfloat16*)g_xl4[0])[i] = __float2bfloat16(v - __bfloat162float(h));
    }
}

// ---------------------------------------------------------------------------
// proj (unchanged, fp32): g_P[t][r][b] = inp[t,b,:]·Win[r,:] + bias[r]
// ---------------------------------------------------------------------------
__global__ __launch_bounds__(128) void proj_kernel(const float* __restrict__ inp,
                                                   const float* __restrict__ win,
                                                   const float* __restrict__ bias) {
    __shared__ __align__(16) float As[16][64];
    __shared__ __align__(16) float Bs[16][64];
    const int t  = blockIdx.y;
    const int rt = blockIdx.x;
    const int tid = threadIdx.x;
    const int tx = tid & 15;
    const int ty = tid >> 4;

    unsigned long long acc[4][4];
#pragma unroll
    for (int i = 0; i < 4; i++)
#pragma unroll
        for (int j = 0; j < 4; j++) acc[i][j] = 0ULL;

    const int lrow = tid >> 1;
    const int lcol = (tid & 1) * 8;
    const float* Ap = inp + (size_t)t * Bn * Dn + (size_t)lrow * Dn + lcol;
    const float* Bp = win + (size_t)rt * 64 * Dn + (size_t)lrow * Dn + lcol;

    for (int kk = 0; kk < Dn; kk += 16) {
        float4 a0 = *(const float4*)(Ap + kk);
        float4 a1 = *(const float4*)(Ap + kk + 4);
        float4 b0 = *(const float4*)(Bp + kk);
        float4 b1 = *(const float4*)(Bp + kk + 4);
        __syncthreads();
        As[lcol + 0][lrow] = a0.x; As[lcol + 1][lrow] = a0.y;
        As[lcol + 2][lrow] = a0.z; As[lcol + 3][lrow] = a0.w;
        As[lcol + 4][lrow] = a1.x; As[lcol + 5][lrow] = a1.y;
        As[lcol + 6][lrow] = a1.z; As[lcol + 7][lrow] = a1.w;
        Bs[lcol + 0][lrow] = b0.x; Bs[lcol + 1][lrow] = b0.y;
        Bs[lcol + 2][lrow] = b0.z; Bs[lcol + 3][lrow] = b0.w;
        Bs[lcol + 4][lrow] = b1.x; Bs[lcol + 5][lrow] = b1.y;
        Bs[lcol + 6][lrow] = b1.z; Bs[lcol + 7][lrow] = b1.w;
        __syncthreads();
#pragma unroll
        for (int k = 0; k < 16; k++) {
            float4 av = *(const float4*)&As[k][tx * 4];
            unsigned long long ad0 = pack2(av.x, av.x);
            unsigned long long ad1 = pack2(av.y, av.y);
            unsigned long long ad2 = pack2(av.z, av.z);
            unsigned long long ad3 = pack2(av.w, av.w);
            ulonglong2 w0 = *(const ulonglong2*)&Bs[k][ty * 8];
            ulonglong2 w1 = *(const ulonglong2*)&Bs[k][ty * 8 + 4];
            ffma2(acc[0][0], ad0, w0.x); ffma2(acc[0][1], ad0, w0.y);
            ffma2(acc[0][2], ad0, w1.x); ffma2(acc[0][3], ad0, w1.y);
            ffma2(acc[1][0], ad1, w0.x); ffma2(acc[1][1], ad1, w0.y);
            ffma2(acc[1][2], ad1, w1.x); ffma2(acc[1][3], ad1, w1.y);
            ffma2(acc[2][0], ad2, w0.x); ffma2(acc[2][1], ad2, w0.y);
            ffma2(acc[2][2], ad2, w1.x); ffma2(acc[2][3], ad2, w1.y);
            ffma2(acc[3][0], ad3, w0.x); ffma2(acc[3][1], ad3, w0.y);
            ffma2(acc[3][2], ad3, w1.x); ffma2(acc[3][3], ad3, w1.y);
        }
    }

    float c[4][8];
#pragma unroll
    for (int bb = 0; bb < 4; bb++)
#pragma unroll
        for (int rp = 0; rp < 4; rp++) {
            float lo, hi;
            unpack2(acc[bb][rp], lo, hi);
            c[bb][rp * 2] = lo;
            c[bb][rp * 2 + 1] = hi;
        }
#pragma unroll
    for (int j = 0; j < 8; j++) {
        int r = rt * 64 + ty * 8 + j;
        float bv = bias[r];
        float4 o = make_float4(c[0][j] + bv, c[1][j] + bv, c[2][j] + bv, c[3][j] + bv);
        *(float4*)&g_P[((size_t)t * Rn + r) * Bn + tx * 4] = o;
    }
}

// ---------------------------------------------------------------------------
// step: HMMA split-bf16 recurrence GEMM, cluster(8) k-split, DSMEM reduce,
// 4-stage cp.async pipeline, ldmatrix fragment loads, split accumulators
// (d_hh/d_hl/d_lh independent chains -> 12 chains/warp).
// grid (8, 32) = 256 CTAs, block 256, 82KB dynamic smem (2 CTAs/SM).
// ---------------------------------------------------------------------------
__global__ __launch_bounds__(256) __cluster_dims__(KSPLIT, 1, 1)
void step_hmma_kernel(const int* __restrict__ lengths,
                      float* __restrict__ out,
                      int t) {
    extern __shared__ __align__(16) char sAll[];     // NSTAGE * BUFSZ
    const int ks  = blockIdx.x;   // cluster rank = k-slice
    const int rt  = blockIdx.y;
    const int tid = threadIdx.x;
    const int wid = tid >> 5, lane = tid & 31;
    const int g = lane >> 2, tig = lane & 3;
    const int mt = wid & 3, nh = wid >> 2;
    const int r0 = rt * MCTA, k0 = ks * KCTA;

    const __nv_bfloat16* Wh  = (const __nv_bfloat16*)g_Whi4;
    const __nv_bfloat16* Wl  = (const __nv_bfloat16*)g_Wlo4;
    const __nv_bfloat16* xhs = (const __nv_bfloat16*)g_xh4[t & 1];
    const __nv_bfloat16* xls = (const __nv_bfloat16*)g_xl4[t & 1];
    __nv_bfloat16* xhd = (__nv_bfloat16*)g_xh4[(t & 1) ^ 1];
    __nv_bfloat16* xld = (__nv_bfloat16*)g_xl4[(t & 1) ^ 1];

    float d_hh[4][4], d_hl[4][4], d_lh[4][4];
#pragma unroll
    for (int i = 0; i < 4; i++)
#pragma unroll
        for (int j = 0; j < 4; j++) { d_hh[i][j] = 0.0f; d_hl[i][j] = 0.0f; d_lh[i][j] = 0.0f; }

    // staging map: one uint4 per thread per plane per chunk
    const int srow = tid >> 2;
    const int sc4  = tid & 3;
    const uint32_t soff = (uint32_t)(srow * ROWB + sc4 * 16);
    const uint32_t sb = smem_u32(sAll);

    auto issue = [&](int c) {
        const uint32_t base = sb + (uint32_t)((c & (NSTAGE - 1)) * BUFSZ);
        const int kk = k0 + c * KCH + sc4 * 8;
        cp16(base + 0 * PLANE + soff, Wh  + (size_t)(r0 + srow) * Rn + kk);
        cp16(base + 1 * PLANE + soff, Wl  + (size_t)(r0 + srow) * Rn + kk);
        cp16(base + 2 * PLANE + soff, xhs + (size_t)srow * Rn + kk);
        cp16(base + 3 * PLANE + soff, xls + (size_t)srow * Rn + kk);
        CP_COMMIT();
    };

    issue(0); issue(1); issue(2);

    // ldmatrix per-lane row offsets (bytes within a plane):
    // A (x4): mats [m0-7,k0-7],[m8-15,k0-7],[m0-7,k8-15],[m8-15,k8-15]
    const int a_rin  = lane & 7;
    const int a_mhi  = (lane >> 3) & 1;        // +8 rows for mats 1,3
    const int a_khi  = (lane >> 4) & 1;        // +16 bytes for mats 2,3
    const uint32_t aoff = (uint32_t)((mt * 16 + a_rin + a_mhi * 8) * ROWB + a_khi * 16);
    // B (x4): mats = 4 n-tiles of this warp's 32-row n-half; lane -> one n row
    const uint32_t boff = (uint32_t)((nh * 32 + lane) * ROWB);

    for (int c = 0; c < NCHUNK; c++) {
        if (c + 3 < NCHUNK) CP_WAIT(2); else CP_WAIT(0);
        __syncthreads();
        if (c + 3 < NCHUNK) issue(c + 3);
        const uint32_t buf = sb + (uint32_t)((c & (NSTAGE - 1)) * BUFSZ);
        const uint32_t AH = buf,             AL = buf + PLANE;
        const uint32_t BH = buf + 2 * PLANE, BL = buf + 3 * PLANE;
#pragma unroll
        for (int ki = 0; ki < KCH / 16; ki++) {
            const uint32_t kseg = (uint32_t)(ki * 32);   // bytes
            uint32_t ah0, ah1, ah2, ah3, al0, al1, al2, al3;
            ldsm4(ah0, ah1, ah2, ah3, AH + aoff + kseg);
            ldsm4(al0, al1, al2, al3, AL + aoff + kseg);
            uint32_t bh0[4], bh1[4], bl0[4], bl1[4];
            ldsm4(bh0[0], bh0[1], bh0[2], bh0[3], BH + boff + kseg);
            ldsm4(bh1[0], bh1[1], bh1[2], bh1[3], BH + boff + kseg + 16);
            ldsm4(bl0[0], bl0[1], bl0[2], bl0[3], BL + boff + kseg);
            ldsm4(bl1[0], bl1[1], bl1[2], bl1[3], BL + boff + kseg + 16);
#pragma unroll
            for (int nt = 0; nt < 4; nt++) {
                mma16816(d_hh[nt], ah0, ah1, ah2, ah3, bh0[nt], bh1[nt]);   // Whi*xhi
                mma16816(d_hl[nt], ah0, ah1, ah2, ah3, bl0[nt], bl1[nt]);   // Whi*xlo
                mma16816(d_lh[nt], al0, al1, al2, al3, bh0[nt], bh1[nt]);   // Wlo*xhi
            }
        }
        __syncthreads();   // stage consumed before refill (ring distance = NSTAGE)
    }

    // combine (fixed order -> deterministic), partial [64r][64n] fp32 at sAll
    float* part = (float*)sAll;
#pragma unroll
    for (int nt = 0; nt < 4; nt++) {
        const int n = nh * 32 + nt * 8 + 2 * tig;
        const int r = mt * 16 + g;
        float v0 = d_hh[nt][0] + (d_hl[nt][0] + d_lh[nt][0]);
        float v1 = d_hh[nt][1] + (d_hl[nt][1] + d_lh[nt][1]);
        float v2 = d_hh[nt][2] + (d_hl[nt][2] + d_lh[nt][2]);
        float v3 = d_hh[nt][3] + (d_hl[nt][3] + d_lh[nt][3]);
        *(float2*)&part[r * 64 + n]       = make_float2(v0, v1);
        *(float2*)&part[(r + 8) * 64 + n] = make_float2(v2, v3);
    }
    __syncthreads();   // partial complete (release)
    CLUSTER_ARRIVE();  // barrier #1: my partial is published

    // prefetch epilogue operands behind arrival skew.
    // This CTA reduces rows [r0 + ks*8, +8): 512 values, 2 consecutive r per thread.
    const int b    = tid & 63;
    const int rloc = ks * 8 + (tid >> 6) * 2;
    const int r    = r0 + rloc;
    float pv[2], xo[2];
#pragma unroll
    for (int j = 0; j < 2; j++) {
        pv[j] = g_P[((size_t)t * Rn + r + j) * Bn + b];
        xo[j] = __bfloat162float(xhs[(size_t)b * Rn + r + j])
              + __bfloat162float(xls[(size_t)b * Rn + r + j]);
    }
    const int len = lengths[b];

    CLUSTER_WAIT();    // barrier #1 wait: all partials visible

    float pr[KSPLIT][2];
#pragma unroll
    for (int peer = 0; peer < KSPLIT; peer++) {
#pragma unroll
        for (int j = 0; j < 2; j++) {
            uint32_t addr = mapa_cluster(sb + (uint32_t)((rloc + j) * 64 + b) * 4u, (uint32_t)peer);
            pr[peer][j] = ld_dsmem_f32(addr);
        }
    }

    CLUSTER_ARRIVE();  // barrier #2: done reading peer SMEM

    const float m = (len > t) ? 0.5f : 0.0f;   // mask * lr (lr = 1-lr = 0.5)
    float2 ov;
#pragma unroll
    for (int j = 0; j < 2; j++) {
        float sum = pv[j];
#pragma unroll
        for (int peer = 0; peer < KSPLIT; peer++) sum += pr[peer][j];   // fixed order
        const float xn = m * (xo[j] + tanh_acc(sum));
        ((float*)&ov)[j] = xn;
        const __nv_bfloat16 h = __float2bfloat16(xn);
        xhd[(size_t)b * Rn + r + j] = h;
        xld[(size_t)b * Rn + r + j] = __float2bfloat16(xn - __bfloat162float(h));
    }
    *(float2*)&out[((size_t)b * Tn + t) * Rn + r] = ov;

    CLUSTER_WAIT();    // barrier #2 wait: safe to exit
}

// ---------------------------------------------------------------------------
// launch: prep + init + proj + 256 HMMA step kernels — all graph-capturable
// ---------------------------------------------------------------------------
extern "C" void kernel_launch(void* const* d_in, const int* in_sizes, int n_in,
                              void* d_out, int out_size) {
    const float* inp     = (const float*)d_in[0];  // [T,B,D]
    const int*   lengths = (const int*)d_in[1];    // [B]
    const float* win     = (const float*)d_in[2];  // [R,D]
    const float* wres    = (const float*)d_in[3];  // [R,R]
    const float* bias    = (const float*)d_in[4];  // [R]
    const float* x0in    = (const float*)d_in[5];  // [R]
    float* out = (float*)d_out;                    // [B,T,R]

    // host-side function attribute; idempotent, not a stream/alloc op
    cudaFuncSetAttribute(step_hmma_kernel, cudaFuncAttributeMaxDynamicSharedMemorySize, SMEM_DYN);

    prep_w_kernel<<<(Rn * Rn / 8 + 255) / 256, 256>>>(wres);
    init_x_kernel<<<(Bn * Rn + 255) / 256, 256>>>(x0in);
    proj_kernel<<<dim3(Rn / 64, Tn), 128>>>(inp, win, bias);
    for (int t = 0; t < Tn; t++) {
        step_hmma_kernel<<<dim3(KSPLIT, NRT), 256, SMEM_DYN>>>(lengths, out, t);
    }
}

// round 17
// speedup vs baseline: 2.9823x; 1.0013x over previous
#include <cuda_runtime.h>
#include <cuda_bf16.h>
#include <cstdint>

#define Tn 256
#define Bn 64
#define Dn 768
#define Rn 2048

#define KSPLIT 8
#define KCTA   (Rn / KSPLIT)   // 256
#define MCTA   64              // rows per CTA
#define NRT    (Rn / MCTA)     // 32 r-tiles
#define KCH    32              // k per chunk
#define NCHUNK (KCTA / KCH)    // 8
#define STRIDE 40              // bf16 elems per smem row (32 + 8 pad)
#define ROWB   (STRIDE * 2)    // 80 bytes per row
#define PLANE  (64 * ROWB)     // 5120 B per plane
#define BUFSZ  (4 * PLANE)     // 20480 B per stage (Whi,Wlo,Xhi,Xlo)
#define NSTAGE 4
#define SMEM_DYN (NSTAGE * BUFSZ)  // 81920 B

// Scratch (static __device__ arrays: allocation-guard safe)
__device__ float g_P[(size_t)Tn * Rn * Bn];            // [t][r][b] proj + bias
__device__ uint4 g_Whi4[(size_t)Rn * Rn / 8];          // bf16 W_hi [r][k]
__device__ uint4 g_Wlo4[(size_t)Rn * Rn / 8];          // bf16 W_lo [r][k]
__device__ uint4 g_xh4[2][(size_t)Bn * Rn / 8];        // bf16 x_hi [b][r] ping-pong
__device__ uint4 g_xl4[2][(size_t)Bn * Rn / 8];        // bf16 x_lo [b][r] ping-pong

// ---- packed f32x2 helpers (proj kernel) ----
__device__ __forceinline__ void ffma2(unsigned long long& d, unsigned long long a, unsigned long long b) {
    asm("fma.rn.f32x2 %0, %1, %2, %0;" : "+l"(d) : "l"(a), "l"(b));
}
__device__ __forceinline__ unsigned long long pack2(float lo, float hi) {
    unsigned long long r;
    asm("mov.b64 %0, {%1, %2};" : "=l"(r) : "f"(lo), "f"(hi));
    return r;
}
__device__ __forceinline__ void unpack2(unsigned long long v, float& lo, float& hi) {
    asm("mov.b64 {%0, %1}, %2;" : "=f"(lo), "=f"(hi) : "l"(v));
}

// ---- cluster / DSMEM helpers ----
__device__ __forceinline__ uint32_t smem_u32(const void* p) {
    uint32_t a;
    asm("{ .reg .u64 t; cvta.to.shared.u64 t, %1; cvt.u32.u64 %0, t; }" : "=r"(a) : "l"(p));
    return a;
}
__device__ __forceinline__ uint32_t mapa_cluster(uint32_t local_addr, uint32_t rank) {
    uint32_t r;
    asm("mapa.shared::cluster.u32 %0, %1, %2;" : "=r"(r) : "r"(local_addr), "r"(rank));
    return r;
}
__device__ __forceinline__ float ld_dsmem_f32(uint32_t addr) {
    float v;
    asm volatile("ld.shared::cluster.f32 %0, [%1];" : "=f"(v) : "r"(addr));
    return v;
}
#define CLUSTER_ARRIVE() asm volatile("barrier.cluster.arrive.aligned;" ::: "memory")
#define CLUSTER_WAIT()   asm volatile("barrier.cluster.wait.aligned;" ::: "memory")

// ---- cp.async helpers ----
__device__ __forceinline__ void cp16(uint32_t smem_addr, const void* gptr) {
    asm volatile("cp.async.cg.shared.global [%0], [%1], 16;" :: "r"(smem_addr), "l"(gptr));
}
#define CP_COMMIT() asm volatile("cp.async.commit_group;" ::: "memory")
#define CP_WAIT(n)  asm volatile("cp.async.wait_group %0;" :: "n"(n) : "memory")

// ---- ldmatrix ----
__device__ __forceinline__ void ldsm4(uint32_t& r0, uint32_t& r1, uint32_t& r2, uint32_t& r3,
                                      uint32_t addr) {
    asm volatile("ldmatrix.sync.aligned.m8n8.x4.shared.b16 {%0,%1,%2,%3}, [%4];"
        : "=r"(r0), "=r"(r1), "=r"(r2), "=r"(r3) : "r"(addr));
}

// accurate tanh independent of fast-math flags (~1e-6 rel)
__device__ __forceinline__ float tanh_acc(float x) {
    float ax = fabsf(x);
    float e  = __expf(-2.0f * ax);
    float r  = (1.0f - e) / (1.0f + e);
    return copysignf(r, x);
}

// m16n8k16 row.col bf16 MMA, fp32 accumulate in-place
__device__ __forceinline__ void mma16816(float* d, uint32_t a0, uint32_t a1, uint32_t a2, uint32_t a3,
                                         uint32_t b0, uint32_t b1) {
    asm volatile(
        "mma.sync.aligned.m16n8k16.row.col.f32.bf16.bf16.f32 "
        "{%0,%1,%2,%3}, {%4,%5,%6,%7}, {%8,%9}, {%0,%1,%2,%3};"
        : "+f"(d[0]), "+f"(d[1]), "+f"(d[2]), "+f"(d[3])
        : "r"(a0), "r"(a1), "r"(a2), "r"(a3), "r"(b0), "r"(b1));
}

// ---------------------------------------------------------------------------
// prep: split W into bf16 hi/lo (deterministic, runs every replay)
// ---------------------------------------------------------------------------
__global__ void prep_w_kernel(const float* __restrict__ w) {
    size_t i = (size_t)blockIdx.x * blockDim.x + threadIdx.x;   // one uint4 (8 bf16)
    if (i >= (size_t)Rn * Rn / 8) return;
    const float4* w4 = (const float4*)w;
    float4 f0 = __ldcs(&w4[i * 2]), f1 = __ldcs(&w4[i * 2 + 1]);
    float f[8] = {f0.x, f0.y, f0.z, f0.w, f1.x, f1.y, f1.z, f1.w};
    union { __nv_bfloat16 h[8]; uint4 v; } hi, lo;
#pragma unroll
    for (int j = 0; j < 8; j++) {
        hi.h[j] = __float2bfloat16(f[j]);
        lo.h[j] = __float2bfloat16(f[j] - __bfloat162float(hi.h[j]));
    }
    g_Whi4[i] = hi.v;
    g_Wlo4[i] = lo.v;
}

// ---------------------------------------------------------------------------
// init: x_hi/x_lo parity-0 buffers from initial_state
// ---------------------------------------------------------------------------
__global__ void init_x_kernel(const float* __restrict__ init_state) {
    int i = blockIdx.x * blockDim.x + threadIdx.x;   // b*Rn + r
    if (i < Bn * Rn) {
        float v = init_state[i & (Rn - 1)];
        __nv_bfloat16 h = __float2bfloat16(v);
        ((__nv_bfloat16*)g_xh4[0])[i] = h;
        ((__nv_bfloat16*)g_xl4[0])[i] = __float2bfloat16(v - __bfloat162float(h));
    }
}

// ---------------------------------------------------------------------------
// proj (fp32): g_P[t][r][b] = inp[t,b,:]·Win[r,:] + bias[r]
// P writes use .cs (evict-first) — P is stream-once data and must not evict
// the W weights from L2 (the recurrence's working set).
// ---------------------------------------------------------------------------
__global__ __launch_bounds__(128) void proj_kernel(const float* __restrict__ inp,
                                                   const float* __restrict__ win,
                                                   const float* __restrict__ bias) {
    __shared__ __align__(16) float As[16][64];
    __shared__ __align__(16) float Bs[16][64];
    const int t  = blockIdx.y;
    const int rt = blockIdx.x;
    const int tid = threadIdx.x;
    const int tx = tid & 15;
    const int ty = tid >> 4;

    unsigned long long acc[4][4];
#pragma unroll
    for (int i = 0; i < 4; i++)
#pragma unroll
        for (int j = 0; j < 4; j++) acc[i][j] = 0ULL;

    const int lrow = tid >> 1;
    const int lcol = (tid & 1) * 8;
    const float* Ap = inp + (size_t)t * Bn * Dn + (size_t)lrow * Dn + lcol;
    const float* Bp = win + (size_t)rt * 64 * Dn + (size_t)lrow * Dn + lcol;

    for (int kk = 0; kk < Dn; kk += 16) {
        float4 a0 = *(const float4*)(Ap + kk);
        float4 a1 = *(const float4*)(Ap + kk + 4);
        float4 b0 = *(const float4*)(Bp + kk);
        float4 b1 = *(const float4*)(Bp + kk + 4);
        __syncthreads();
        As[lcol + 0][lrow] = a0.x; As[lcol + 1][lrow] = a0.y;
        As[lcol + 2][lrow] = a0.z; As[lcol + 3][lrow] = a0.w;
        As[lcol + 4][lrow] = a1.x; As[lcol + 5][lrow] = a1.y;
        As[lcol + 6][lrow] = a1.z; As[lcol + 7][lrow] = a1.w;
        Bs[lcol + 0][lrow] = b0.x; Bs[lcol + 1][lrow] = b0.y;
        Bs[lcol + 2][lrow] = b0.z; Bs[lcol + 3][lrow] = b0.w;
        Bs[lcol + 4][lrow] = b1.x; Bs[lcol + 5][lrow] = b1.y;
        Bs[lcol + 6][lrow] = b1.z; Bs[lcol + 7][lrow] = b1.w;
        __syncthreads();
#pragma unroll
        for (int k = 0; k < 16; k++) {
            float4 av = *(const float4*)&As[k][tx * 4];
            unsigned long long ad0 = pack2(av.x, av.x);
            unsigned long long ad1 = pack2(av.y, av.y);
            unsigned long long ad2 = pack2(av.z, av.z);
            unsigned long long ad3 = pack2(av.w, av.w);
            ulonglong2 w0 = *(const ulonglong2*)&Bs[k][ty * 8];
            ulonglong2 w1 = *(const ulonglong2*)&Bs[k][ty * 8 + 4];
            ffma2(acc[0][0], ad0, w0.x); ffma2(acc[0][1], ad0, w0.y);
            ffma2(acc[0][2], ad0, w1.x); ffma2(acc[0][3], ad0, w1.y);
            ffma2(acc[1][0], ad1, w0.x); ffma2(acc[1][1], ad1, w0.y);
            ffma2(acc[1][2], ad1, w1.x); ffma2(acc[1][3], ad1, w1.y);
            ffma2(acc[2][0], ad2, w0.x); ffma2(acc[2][1], ad2, w0.y);
            ffma2(acc[2][2], ad2, w1.x); ffma2(acc[2][3], ad2, w1.y);
            ffma2(acc[3][0], ad3, w0.x); ffma2(acc[3][1], ad3, w0.y);
            ffma2(acc[3][2], ad3, w1.x); ffma2(acc[3][3], ad3, w1.y);
        }
    }

    float c[4][8];
#pragma unroll
    for (int bb = 0; bb < 4; bb++)
#pragma unroll
        for (int rp = 0; rp < 4; rp++) {
            float lo, hi;
            unpack2(acc[bb][rp], lo, hi);
            c[bb][rp * 2] = lo;
            c[bb][rp * 2 + 1] = hi;
        }
#pragma unroll
    for (int j = 0; j < 8; j++) {
        int r = rt * 64 + ty * 8 + j;
        float bv = bias[r];
        float4 o = make_float4(c[0][j] + bv, c[1][j] + bv, c[2][j] + bv, c[3][j] + bv);
        __stcs((float4*)&g_P[((size_t)t * Rn + r) * Bn + tx * 4], o);   // evict-first
    }
}

// ---------------------------------------------------------------------------
// step: HMMA split-bf16 recurrence GEMM, cluster(8) k-split, DSMEM reduce,
// 4-stage cp.async pipeline, ldmatrix, split accumulators.
// All streaming traffic (P reads, out writes) uses .cs evict-first so the
// 16.8MB W working set stays L2-resident across the 256 steps.
// ---------------------------------------------------------------------------
__global__ __launch_bounds__(256) __cluster_dims__(KSPLIT, 1, 1)
void step_hmma_kernel(const int* __restrict__ lengths,
                      float* __restrict__ out,
                      int t) {
    extern __shared__ __align__(16) char sAll[];     // NSTAGE * BUFSZ
    const int ks  = blockIdx.x;   // cluster rank = k-slice
    const int rt  = blockIdx.y;
    const int tid = threadIdx.x;
    const int wid = tid >> 5, lane = tid & 31;
    const int g = lane >> 2, tig = lane & 3;
    const int mt = wid & 3, nh = wid >> 2;
    const int r0 = rt * MCTA, k0 = ks * KCTA;

    const __nv_bfloat16* Wh  = (const __nv_bfloat16*)g_Whi4;
    const __nv_bfloat16* Wl  = (const __nv_bfloat16*)g_Wlo4;
    const __nv_bfloat16* xhs = (const __nv_bfloat16*)g_xh4[t & 1];
    const __nv_bfloat16* xls = (const __nv_bfloat16*)g_xl4[t & 1];
    __nv_bfloat16* xhd = (__nv_bfloat16*)g_xh4[(t & 1) ^ 1];
    __nv_bfloat16* xld = (__nv_bfloat16*)g_xl4[(t & 1) ^ 1];

    float d_hh[4][4], d_hl[4][4], d_lh[4][4];
#pragma unroll
    for (int i = 0; i < 4; i++)
#pragma unroll
        for (int j = 0; j < 4; j++) { d_hh[i][j] = 0.0f; d_hl[i][j] = 0.0f; d_lh[i][j] = 0.0f; }

    // staging map: one uint4 per thread per plane per chunk
    const int srow = tid >> 2;
    const int sc4  = tid & 3;
    const uint32_t soff = (uint32_t)(srow * ROWB + sc4 * 16);
    const uint32_t sb = smem_u32(sAll);

    auto issue = [&](int c) {
        const uint32_t base = sb + (uint32_t)((c & (NSTAGE - 1)) * BUFSZ);
        const int kk = k0 + c * KCH + sc4 * 8;
        cp16(base + 0 * PLANE + soff, Wh  + (size_t)(r0 + srow) * Rn + kk);
        cp16(base + 1 * PLANE + soff, Wl  + (size_t)(r0 + srow) * Rn + kk);
        cp16(base + 2 * PLANE + soff, xhs + (size_t)srow * Rn + kk);
        cp16(base + 3 * PLANE + soff, xls + (size_t)srow * Rn + kk);
        CP_COMMIT();
    };

    issue(0); issue(1); issue(2);

    // ldmatrix per-lane row offsets (bytes within a plane)
    const int a_rin  = lane & 7;
    const int a_mhi  = (lane >> 3) & 1;
    const int a_khi  = (lane >> 4) & 1;
    const uint32_t aoff = (uint32_t)((mt * 16 + a_rin + a_mhi * 8) * ROWB + a_khi * 16);
    const uint32_t boff = (uint32_t)((nh * 32 + lane) * ROWB);

    for (int c = 0; c < NCHUNK; c++) {
        if (c + 3 < NCHUNK) CP_WAIT(2); else CP_WAIT(0);
        __syncthreads();
        if (c + 3 < NCHUNK) issue(c + 3);
        const uint32_t buf = sb + (uint32_t)((c & (NSTAGE - 1)) * BUFSZ);
        const uint32_t AH = buf,             AL = buf + PLANE;
        const uint32_t BH = buf + 2 * PLANE, BL = buf + 3 * PLANE;
#pragma unroll
        for (int ki = 0; ki < KCH / 16; ki++) {
            const uint32_t kseg = (uint32_t)(ki * 32);   // bytes
            uint32_t ah0, ah1, ah2, ah3, al0, al1, al2, al3;
            ldsm4(ah0, ah1, ah2, ah3, AH + aoff + kseg);
            ldsm4(al0, al1, al2, al3, AL + aoff + kseg);
            uint32_t bh0[4], bh1[4], bl0[4], bl1[4];
            ldsm4(bh0[0], bh0[1], bh0[2], bh0[3], BH + boff + kseg);
            ldsm4(bh1[0], bh1[1], bh1[2], bh1[3], BH + boff + kseg + 16);
            ldsm4(bl0[0], bl0[1], bl0[2], bl0[3], BL + boff + kseg);
            ldsm4(bl1[0], bl1[1], bl1[2], bl1[3], BL + boff + kseg + 16);
#pragma unroll
            for (int nt = 0; nt < 4; nt++) {
                mma16816(d_hh[nt], ah0, ah1, ah2, ah3, bh0[nt], bh1[nt]);   // Whi*xhi
                mma16816(d_hl[nt], ah0, ah1, ah2, ah3, bl0[nt], bl1[nt]);   // Whi*xlo
                mma16816(d_lh[nt], al0, al1, al2, al3, bh0[nt], bh1[nt]);   // Wlo*xhi
            }
        }
        __syncthreads();   // stage consumed before refill (ring distance = NSTAGE)
    }

    // combine (fixed order -> deterministic), partial [64r][64n] fp32 at sAll
    float* part = (float*)sAll;
#pragma unroll
    for (int nt = 0; nt < 4; nt++) {
        const int n = nh * 32 + nt * 8 + 2 * tig;
        const int r = mt * 16 + g;
        float v0 = d_hh[nt][0] + (d_hl[nt][0] + d_lh[nt][0]);
        float v1 = d_hh[nt][1] + (d_hl[nt][1] + d_lh[nt][1]);
        float v2 = d_hh[nt][2] + (d_hl[nt][2] + d_lh[nt][2]);
        float v3 = d_hh[nt][3] + (d_hl[nt][3] + d_lh[nt][3]);
        *(float2*)&part[r * 64 + n]       = make_float2(v0, v1);
        *(float2*)&part[(r + 8) * 64 + n] = make_float2(v2, v3);
    }
    __syncthreads();   // partial complete (release)
    CLUSTER_ARRIVE();  // barrier #1: my partial is published

    // prefetch epilogue operands behind arrival skew.
    const int b    = tid & 63;
    const int rloc = ks * 8 + (tid >> 6) * 2;
    const int r    = r0 + rloc;
    float pv[2], xo[2];
#pragma unroll
    for (int j = 0; j < 2; j++) {
        pv[j] = __ldcs(&g_P[((size_t)t * Rn + r + j) * Bn + b]);   // evict-first (stream-once)
        xo[j] = __bfloat162float(xhs[(size_t)b * Rn + r + j])
              + __bfloat162float(xls[(size_t)b * Rn + r + j]);
    }
    const int len = lengths[b];

    CLUSTER_WAIT();    // barrier #1 wait: all partials visible

    float pr[KSPLIT][2];
#pragma unroll
    for (int peer = 0; peer < KSPLIT; peer++) {
#pragma unroll
        for (int j = 0; j < 2; j++) {
            uint32_t addr = mapa_cluster(sb + (uint32_t)((rloc + j) * 64 + b) * 4u, (uint32_t)peer);
            pr[peer][j] = ld_dsmem_f32(addr);
        }
    }

    CLUSTER_ARRIVE();  // barrier #2: done reading peer SMEM

    const float m = (len > t) ? 0.5f : 0.0f;   // mask * lr (lr = 1-lr = 0.5)
    float2 ov;
#pragma unroll
    for (int j = 0; j < 2; j++) {
        float sum = pv[j];
#pragma unroll
        for (int peer = 0; peer < KSPLIT; peer++) sum += pr[peer][j];   // fixed order
        const float xn = m * (xo[j] + tanh_acc(sum));
        ((float*)&ov)[j] = xn;
        const __nv_bfloat16 h = __float2bfloat16(xn);
        xhd[(size_t)b * Rn + r + j] = h;
        xld[(size_t)b * Rn + r + j] = __float2bfloat16(xn - __bfloat162float(h));
    }
    __stcs((float2*)&out[((size_t)b * Tn + t) * Rn + r], ov);   // evict-first (stream-once)

    CLUSTER_WAIT();    // barrier #2 wait: safe to exit
}

// ---------------------------------------------------------------------------
// launch: prep + init + proj + 256 HMMA step kernels — all graph-capturable
// ---------------------------------------------------------------------------
extern "C" void kernel_launch(void* const* d_in, const int* in_sizes, int n_in,
                              void* d_out, int out_size) {
    const float* inp     = (const float*)d_in[0];  // [T,B,D]
    const int*   lengths = (const int*)d_in[1];    // [B]
    const float* win     = (const float*)d_in[2];  // [R,D]
    const float* wres    = (const float*)d_in[3];  // [R,R]
    const float* bias    = (const float*)d_in[4];  // [R]
    const float* x0in    = (const float*)d_in[5];  // [R]
    float* out = (float*)d_out;                    // [B,T,R]

    // host-side function attribute; idempotent, not a stream/alloc op
    cudaFuncSetAttribute(step_hmma_kernel, cudaFuncAttributeMaxDynamicSharedMemorySize, SMEM_DYN);

    prep_w_kernel<<<(Rn * Rn / 8 + 255) / 256, 256>>>(wres);
    init_x_kernel<<<(Bn * Rn + 255) / 256, 256>>>(x0in);
    proj_kernel<<<dim3(Rn / 64, Tn), 128>>>(inp, win, bias);
    for (int t = 0; t < Tn; t++) {
        step_hmma_kernel<<<dim3(KSPLIT, NRT), 256, SMEM_DYN>>>(lengths, out, t);
    }
}